// round 11
// baseline (speedup 1.0000x reference)
#include <cuda_runtime.h>
#include <cuda_bf16.h>
#include <cstdint>

// Problem constants
#define Hn 1024
#define Bn 128
#define Tn 400
#define Sn 64
#define Cn 8
#define NOUTn 3
#define NCLSn 3
#define BOTn 2
#define CLSOUTn 8
#define NEXC 819              // int(1024 * 0.8)

#define NCTA 128
#define NTHR 256
#define JPC 8                 // j columns per CTA in phase B
#define KSL 128               // k-slice per CTA in phase A
#define JSL 64                // j-slice per CTA in phase A
#define NKC 8                 // number of k slices

#define ALPHA_N 0.2f
#define DT_SEC 0.02f
#define NZ_SCALE 0.25f        // NOISE_STD / ALPHA_N
#define AX_SLOW ((float)(20.0 / 1500.0))
#define AX_FAST ((float)(20.0 / 200.0))

#define NR (NOUTn + NCLSn * CLSOUTn)   // 27 fused readout rows
#define PR_ROWS 32

// smem word offsets
#define W_PITCH 72            // 64 j + 8 pad (words) -> conflict-free
#define HP_PITCH 136          // 128 b + 8 pad (words) -> conflict-free
#define SM_WHI 0              // 64 * 72 = 4608 words
#define SM_WLO 4608
#define SM_HPHI 9216          // 64 * 136 = 8704 words
#define SM_HPLO 17920         // ends at 26624
#define SM_WIN 26624          // 8 rows x 72 floats (w_in|w_ctx) = 576 words
#define SM_COMB 0             // P3 reuses the space
#define SMEM_WORDS 27648      // comb (27*1024) is the max user
#define SMEM_BYTES (SMEM_WORDS * 4)

// ---------------- device scratch ----------------
__device__ unsigned g_hph[2][(Hn / 2) * Bn];           // h_post hi pairs [k/2][b]
__device__ unsigned g_hpl[2][(Hn / 2) * Bn];           // h_post lo pairs [k/2][b]
__device__ float g_part[2][(size_t)NKC * Hn * Bn];     // [par][kc][j][b]
__device__ float g_comb[NR * Hn];
__device__ float g_combb[NR];
__device__ unsigned g_count;                           // phase-transition counter
__device__ unsigned g_kcnt[NKC * 32];                  // partial-ready counts (padded)
__device__ unsigned g_hcnt[NKC * 32];                  // h_post-ready counts (padded)

// ---------------- sync helpers ----------------
__device__ __forceinline__ void red_rel(unsigned* p) {
    asm volatile("red.release.gpu.global.add.u32 [%0], 1;" :: "l"(p) : "memory");
}
__device__ __forceinline__ unsigned ld_rlx(const unsigned* p) {
    unsigned v;
    asm volatile("ld.relaxed.gpu.global.u32 %0, [%1];" : "=r"(v) : "l"(p) : "memory");
    return v;
}
__device__ __forceinline__ void fence_acq() {
    asm volatile("fence.acq_rel.gpu;" ::: "memory");
}
__device__ __forceinline__ void announce(unsigned* p) {
    __syncthreads();
    if (threadIdx.x == 0) red_rel(p);
}

__device__ __forceinline__ void cp_async16(uint32_t saddr, const void* gaddr) {
    asm volatile("cp.async.cg.shared.global [%0], [%1], 16;" :: "r"(saddr), "l"(gaddr));
}
__device__ __forceinline__ void cp_commit() {
    asm volatile("cp.async.commit_group;");
}
template <int N>
__device__ __forceinline__ void cp_wait() {
    asm volatile("cp.async.wait_group %0;" :: "n"(N));
}

__device__ __forceinline__ void gbar(unsigned target) {
    __syncthreads();
    if (threadIdx.x == 0) {
        red_rel(&g_count);
        while (ld_rlx(&g_count) < target) { }
        fence_acq();
    }
    __syncthreads();
}

// bf16 split helpers
__device__ __forceinline__ unsigned pack_pair_hi(float e, float o,
                                                 float& re, float& ro) {
    __nv_bfloat16 he = __float2bfloat16(e);
    __nv_bfloat16 ho = __float2bfloat16(o);
    re = e - __bfloat162float(he);
    ro = o - __bfloat162float(ho);
    return ((unsigned)__bfloat16_as_ushort(ho) << 16) |
           (unsigned)__bfloat16_as_ushort(he);
}
__device__ __forceinline__ unsigned pack_pair(float e, float o) {
    __nv_bfloat16 he = __float2bfloat16(e);
    __nv_bfloat16 ho = __float2bfloat16(o);
    return ((unsigned)__bfloat16_as_ushort(ho) << 16) |
           (unsigned)__bfloat16_as_ushort(he);
}

#define MMA16816(cr, a0_, a1_, a2_, a3_, b0_, b1_)                          \
    asm volatile("mma.sync.aligned.m16n8k16.row.col.f32.bf16.bf16.f32 "     \
        "{%0,%1,%2,%3}, {%4,%5,%6,%7}, {%8,%9}, {%0,%1,%2,%3};"             \
        : "+f"((cr)[0]), "+f"((cr)[1]), "+f"((cr)[2]), "+f"((cr)[3])        \
        : "r"(a0_), "r"(a1_), "r"(a2_), "r"(a3_), "r"(b0_), "r"(b1_))

// lazy drive: 4 j-rows x (64 stim + 8 ctx) dot + noise, weights from smem rows
__device__ __forceinline__ void compute_drive(
        const float* __restrict__ stim, const float* __restrict__ ctx,
        const float* __restrict__ noise, const float* __restrict__ wsm,
        int b, int g, int jg, int t, float dn[4]) {
    float a0 = 0.f, a1 = 0.f, a2 = 0.f, a3 = 0.f;
    const float4* sp = (const float4*)(stim + ((size_t)b * Tn + t) * Sn);
    const float4* wr = (const float4*)(wsm + (4 * g) * 72);  // row stride 18 f4
    #pragma unroll
    for (int p = 0; p < 16; p++) {
        float4 v  = sp[p];
        float4 w0 = wr[p], w1 = wr[18 + p], w2 = wr[36 + p], w3 = wr[54 + p];
        a0 = fmaf(v.x, w0.x, a0); a0 = fmaf(v.y, w0.y, a0);
        a0 = fmaf(v.z, w0.z, a0); a0 = fmaf(v.w, w0.w, a0);
        a1 = fmaf(v.x, w1.x, a1); a1 = fmaf(v.y, w1.y, a1);
        a1 = fmaf(v.z, w1.z, a1); a1 = fmaf(v.w, w1.w, a1);
        a2 = fmaf(v.x, w2.x, a2); a2 = fmaf(v.y, w2.y, a2);
        a2 = fmaf(v.z, w2.z, a2); a2 = fmaf(v.w, w2.w, a2);
        a3 = fmaf(v.x, w3.x, a3); a3 = fmaf(v.y, w3.y, a3);
        a3 = fmaf(v.z, w3.z, a3); a3 = fmaf(v.w, w3.w, a3);
    }
    const float4* cp4 = (const float4*)(ctx + ((size_t)b * Tn + t) * Cn);
    #pragma unroll
    for (int p = 0; p < 2; p++) {
        float4 v  = cp4[p];
        float4 w0 = wr[16 + p], w1 = wr[34 + p], w2 = wr[52 + p], w3 = wr[70 + p];
        a0 = fmaf(v.x, w0.x, a0); a0 = fmaf(v.y, w0.y, a0);
        a0 = fmaf(v.z, w0.z, a0); a0 = fmaf(v.w, w0.w, a0);
        a1 = fmaf(v.x, w1.x, a1); a1 = fmaf(v.y, w1.y, a1);
        a1 = fmaf(v.z, w1.z, a1); a1 = fmaf(v.w, w1.w, a1);
        a2 = fmaf(v.x, w2.x, a2); a2 = fmaf(v.y, w2.y, a2);
        a2 = fmaf(v.z, w2.z, a2); a2 = fmaf(v.w, w2.w, a2);
        a3 = fmaf(v.x, w3.x, a3); a3 = fmaf(v.y, w3.y, a3);
        a3 = fmaf(v.z, w3.z, a3); a3 = fmaf(v.w, w3.w, a3);
    }
    float4 nz = *(const float4*)(noise + ((size_t)t * Bn + b) * Hn + jg);
    dn[0] = fmaf(NZ_SCALE, nz.x, a0);
    dn[1] = fmaf(NZ_SCALE, nz.y, a1);
    dn[2] = fmaf(NZ_SCALE, nz.z, a2);
    dn[3] = fmaf(NZ_SCALE, nz.w, a3);
}

// ---------------- reset (graph-replay determinism) ----------------
__global__ void reset_kernel() {
    int i = threadIdx.x;
    if (i == 0) g_count = 0;
    if (i < NKC * 32) { g_kcnt[i] = 0; g_hcnt[i] = 0; }
}

// ---------------- the single persistent kernel ----------------
__global__ void __launch_bounds__(NTHR, 1) mega_kernel(
        const float* __restrict__ stim,
        const float* __restrict__ ctx,
        const float* __restrict__ w_rec,
        const float* __restrict__ b_rec,
        const float* __restrict__ w_in,
        const float* __restrict__ w_ctx,
        const float* __restrict__ w_out,
        const float* __restrict__ b_out,
        const float* __restrict__ c1_w,
        const float* __restrict__ c1_b,
        const float* __restrict__ c2_w,
        const float* __restrict__ c2_b,
        const float* __restrict__ noise,
        float* __restrict__ out0,
        float* __restrict__ acts,
        float* __restrict__ pout) {
    extern __shared__ float sm[];
    unsigned* wh  = (unsigned*)(sm + SM_WHI);    // [64 kq][72] pairs
    unsigned* wl  = (unsigned*)(sm + SM_WLO);
    unsigned* hph = (unsigned*)(sm + SM_HPHI);   // [64 kq][136] pairs
    unsigned* hpl = (unsigned*)(sm + SM_HPLO);
    float* wsm    = sm + SM_WIN;                 // 8 rows x 72 (w_in|w_ctx)

    const int c    = blockIdx.x;
    const int tid  = threadIdx.x;
    const int lane = tid & 31;
    const int warp = tid >> 5;            // 0..7 : m-tile (b block 16*warp)
    // phase A roles
    const int kc = c >> 4, jc = c & 15;
    const int kc32 = kc * 32;
    const int la4 = lane & 3, ld4 = lane >> 2;
    const int bb = 16 * warp + ld4;
    // phase B roles
    const int b  = tid & 127;
    const int g  = tid >> 7;              // 0..1
    const int j0 = c * JPC;
    const int jg = j0 + 4 * g;            // 4 columns, jg multiple of 4

    // ---- P0a: classifier fusion ----
    {
        int idx = c * NTHR + tid;
        if (idx < NOUTn * Hn) g_comb[idx] = w_out[idx];
        if (idx < NCLSn * CLSOUTn * Hn) {
            int r = idx / Hn, h = idx % Hn;
            int j = r / CLSOUTn, o = r % CLSOUTn;
            float acc = 0.f;
            #pragma unroll
            for (int k = 0; k < BOTn; k++)
                acc += c2_w[(j * CLSOUTn + o) * BOTn + k] * c1_w[(j * BOTn + k) * Hn + h];
            g_comb[(NOUTn + r) * Hn + h] = acc;
        }
        if (idx < NOUTn) g_combb[idx] = b_out[idx];
        if (idx >= NOUTn && idx < NR) {
            int r = idx - NOUTn;
            int j = r / CLSOUTn, o = r % CLSOUTn;
            float acc = c2_b[j * CLSOUTn + o];
            #pragma unroll
            for (int k = 0; k < BOTn; k++)
                acc += c2_w[(j * CLSOUTn + o) * BOTn + k] * c1_b[j * BOTn + k];
            g_combb[idx] = acc;
        }
    }

    // ---- P0b: W slice as hi/lo bf16 k-pairs ----
    for (int idx = tid; idx < 64 * JSL; idx += NTHR) {
        int kq = idx >> 6, jl = idx & 63;
        int k0 = kc * KSL + 2 * kq, j = jc * JSL + jl;
        float w0 = fmaxf(w_rec[(size_t)k0 * Hn + j], 0.f);
        float w1 = fmaxf(w_rec[(size_t)(k0 + 1) * Hn + j], 0.f);
        if (k0 == j) w0 = 0.f;
        if (k0 + 1 == j) w1 = 0.f;
        w0 = (k0 < NEXC) ? w0 : -w0;
        w1 = (k0 + 1 < NEXC) ? w1 : -w1;
        float r0, r1;
        wh[kq * W_PITCH + jl] = pack_pair_hi(w0, w1, r0, r1);
        wl[kq * W_PITCH + jl] = pack_pair(r0, r1);
    }
    // input-weight rows for this CTA's 8 j columns: [jl][72] = w_in(64)|w_ctx(8)
    for (int idx = tid; idx < JPC * 72; idx += NTHR) {
        int jl = idx / 72, q = idx - jl * 72;
        wsm[jl * 72 + q] = (q < Sn) ? w_in[(size_t)(j0 + jl) * Sn + q]
                                    : w_ctx[(size_t)(j0 + jl) * Cn + (q - Sn)];
    }
    float br[4];
    #pragma unroll
    for (int jj = 0; jj < 4; jj++) br[jj] = b_rec[jg + jj];

    // ---- P0c: initial h_post(0) = 0, announce (syncthreads inside makes wsm visible) ----
    {
        int kq0 = jg >> 1;
        g_hph[0][kq0 * Bn + b] = 0u;
        g_hph[0][(kq0 + 1) * Bn + b] = 0u;
        g_hpl[0][kq0 * Bn + b] = 0u;
        g_hpl[0][(kq0 + 1) * Bn + b] = 0u;
    }
    announce(&g_hcnt[kc32]);

    // drive for step 0 (lazy, in registers)
    float dcur[4];
    compute_drive(stim, ctx, noise, wsm, b, g, jg, 0, dcur);

    // ---- P2: scan ----
    float h[4], sx[4], su[4];
    #pragma unroll
    for (int jj = 0; jj < 4; jj++) {
        h[jj] = 0.f;
        sx[jj] = 1.f;
        su[jj] = (jj & 1) ? 0.15f : 0.45f;   // jg multiple of 4
    }

    const uint32_t hph_addr = (uint32_t)__cvta_generic_to_shared(hph);
    const uint32_t hpl_addr = (uint32_t)__cvta_generic_to_shared(hpl);

    for (int step = 0; step < Tn; step++) {
        const unsigned stp1 = 16u * (unsigned)(step + 1);
        const int par = step & 1;

        // ---- wait: h_post pairs for my k-slice ready (relaxed spin + fence) ----
        if (tid == 0) {
            while (ld_rlx(&g_hcnt[kc32]) < stp1) { }
            fence_acq();
        }
        __syncthreads();

        // ---- phase A: stage hi/lo pair arrays, 2 pipelined stages ----
        {
            const unsigned* srch = g_hph[par] + (size_t)(kc * 64) * Bn;
            const unsigned* srcl = g_hpl[par] + (size_t)(kc * 64) * Bn;
            #pragma unroll
            for (int s = 0; s < 2; s++) {
                int rb = 32 * s;
                #pragma unroll
                for (int i = 0; i < 4; i++) {
                    int id = tid + i * 256;
                    int r = rb + (id >> 5), ch = id & 31;
                    cp_async16(hph_addr + r * (HP_PITCH * 4) + ch * 16,
                               (const char*)srch + r * 512 + ch * 16);
                }
                #pragma unroll
                for (int i = 0; i < 4; i++) {
                    int id = tid + i * 256;
                    int r = rb + (id >> 5), ch = id & 31;
                    cp_async16(hpl_addr + r * (HP_PITCH * 4) + ch * 16,
                               (const char*)srcl + r * 512 + ch * 16);
                }
                cp_commit();
            }
        }

        // ---- MMA GEMM: C[b 16-tile][j 8-tiles] over k=128 ----
        float C[8][4];
        #pragma unroll
        for (int nt = 0; nt < 8; nt++) {
            C[nt][0] = 0.f; C[nt][1] = 0.f; C[nt][2] = 0.f; C[nt][3] = 0.f;
        }

        #pragma unroll
        for (int t = 0; t < 8; t++) {
            if (t == 0) { cp_wait<1>(); __syncthreads(); }
            if (t == 4) { cp_wait<0>(); __syncthreads(); }
            const int kq = 8 * t + la4;
            unsigned ah0 = hph[kq * HP_PITCH + bb];
            unsigned ah1 = hph[kq * HP_PITCH + bb + 8];
            unsigned ah2 = hph[(kq + 4) * HP_PITCH + bb];
            unsigned ah3 = hph[(kq + 4) * HP_PITCH + bb + 8];
            unsigned al0 = hpl[kq * HP_PITCH + bb];
            unsigned al1 = hpl[kq * HP_PITCH + bb + 8];
            unsigned al2 = hpl[(kq + 4) * HP_PITCH + bb];
            unsigned al3 = hpl[(kq + 4) * HP_PITCH + bb + 8];
            #pragma unroll
            for (int nt = 0; nt < 8; nt++) {
                int jo = 8 * nt + ld4;
                unsigned bh0 = wh[kq * W_PITCH + jo];
                unsigned bh1 = wh[(kq + 4) * W_PITCH + jo];
                unsigned bl0 = wl[kq * W_PITCH + jo];
                unsigned bl1 = wl[(kq + 4) * W_PITCH + jo];
                MMA16816(C[nt], ah0, ah1, ah2, ah3, bh0, bh1);
                MMA16816(C[nt], ah0, ah1, ah2, ah3, bl0, bl1);
                MMA16816(C[nt], al0, al1, al2, al3, bh0, bh1);
            }
        }

        // write partials [kc][j][b]
        {
            float* gpart = g_part[par];
            #pragma unroll
            for (int nt = 0; nt < 8; nt++) {
                int j = jc * JSL + 8 * nt + 2 * la4;
                float* p0 = gpart + ((size_t)kc * Hn + j) * Bn;
                p0[bb]          = C[nt][0];
                p0[Bn + bb]     = C[nt][1];
                p0[bb + 8]      = C[nt][2];
                p0[Bn + bb + 8] = C[nt][3];
            }
        }

        announce(&g_kcnt[kc32]);

        // ---- phase B: wait all 8 partial groups (relaxed spins, MLP=8) ----
        if (tid == 0) {
            for (;;) {
                unsigned ok = 1;
                #pragma unroll
                for (int k2 = 0; k2 < NKC; k2++)
                    ok &= (ld_rlx(&g_kcnt[k2 * 32]) >= stp1) ? 1u : 0u;
                if (ok) break;
            }
            fence_acq();
        }
        __syncthreads();

        float s0 = 0.f, s1 = 0.f, s2 = 0.f, s3 = 0.f;
        {
            const float* gpart = g_part[par];
            #pragma unroll
            for (int k2 = 0; k2 < NKC; k2++) {
                const float* pp = gpart + ((size_t)k2 * Hn + jg) * Bn + b;
                s0 += __ldcg(pp);
                s1 += __ldcg(pp + Bn);
                s2 += __ldcg(pp + 2 * Bn);
                s3 += __ldcg(pp + 3 * Bn);
            }
        }
        float ss[4] = {s0, s1, s2, s3};
        float hn[4], hp[4];
        #pragma unroll
        for (int jj = 0; jj < 4; jj++) {
            float val = h[jj] * (1.f - ALPHA_N)
                      + ALPHA_N * (dcur[jj] + ss[jj] + br[jj]);
            hn[jj] = fmaxf(val, 0.f);
            h[jj] = hn[jj];
        }
        // STP + h_post(step+1) pairs, announce, then off-path work
        #pragma unroll
        for (int jj = 0; jj < 4; jj++) {
            const float axv = (jj & 1) ? AX_FAST : AX_SLOW;
            const float Uv  = (jj & 1) ? 0.15f : 0.45f;
            float hh = h[jj];
            float sxo = sx[jj], suo = su[jj];
            float sxn = sxo + axv * (1.f - sxo) - DT_SEC * suo * sxo * hh;
            float sun = suo + axv * (Uv - suo) + DT_SEC * Uv * (1.f - suo) * hh;
            sxn = fminf(fmaxf(sxn, 0.f), 1.f);
            sun = fminf(fmaxf(sun, 0.f), 1.f);
            sx[jj] = sxn; su[jj] = sun;
            hp[jj] = sun * sxn * hh;
        }
        {
            unsigned* dh = g_hph[par ^ 1];
            unsigned* dl = g_hpl[par ^ 1];
            int kq0 = jg >> 1;
            float r0, r1, r2, r3;
            unsigned h01 = pack_pair_hi(hp[0], hp[1], r0, r1);
            unsigned h23 = pack_pair_hi(hp[2], hp[3], r2, r3);
            dh[kq0 * Bn + b]       = h01;
            dh[(kq0 + 1) * Bn + b] = h23;
            dl[kq0 * Bn + b]       = pack_pair(r0, r1);
            dl[(kq0 + 1) * Bn + b] = pack_pair(r2, r3);
        }
        announce(&g_hcnt[kc32]);

        // off critical path: acts store + next step's drive (hidden in wait slack)
        *(float4*)(acts + ((size_t)b * Tn + step) * Hn + jg) =
            make_float4(hn[0], hn[1], hn[2], hn[3]);
        if (step + 1 < Tn)
            compute_drive(stim, ctx, noise, wsm, b, g, jg, step + 1, dcur);
    }

    gbar(NCTA);   // scan complete

    // ---- P3: post (fused readout) ----
    {
        float* s_comb = sm + SM_COMB;
        for (int i = tid; i < NR * Hn; i += NTHR) s_comb[i] = g_comb[i];
        __syncthreads();

        const float4* comb4 = (const float4*)s_comb;

        for (int u = c; u < (Bn * Tn) / PR_ROWS; u += NCTA) {
            #pragma unroll 1
            for (int rr = 0; rr < 4; rr++) {
                const int bt = u * PR_ROWS + warp * 4 + rr;
                const float4* a4 = (const float4*)(acts + (size_t)bt * Hn);

                float acc[NR];
                #pragma unroll
                for (int r = 0; r < NR; r++) acc[r] = 0.f;

                #pragma unroll
                for (int it = 0; it < Hn / 128; it++) {
                    float4 a = a4[it * 32 + lane];
                    #pragma unroll
                    for (int r = 0; r < NR; r++) {
                        float4 ww = comb4[r * 256 + it * 32 + lane];
                        float s = a.x * ww.x + a.y * ww.y;
                        s = fmaf(a.z, ww.z, s);
                        s = fmaf(a.w, ww.w, s);
                        acc[r] += s;
                    }
                }
                #pragma unroll
                for (int r = 0; r < NR; r++) {
                    #pragma unroll
                    for (int off = 16; off > 0; off >>= 1)
                        acc[r] += __shfl_down_sync(0xffffffffu, acc[r], off);
                }
                if (lane == 0) {
                    #pragma unroll
                    for (int r = 0; r < NOUTn; r++)
                        out0[(size_t)bt * NOUTn + r] = acc[r] + g_combb[r];
                    #pragma unroll
                    for (int r = NOUTn; r < NR; r++)
                        pout[(size_t)bt * (NCLSn * CLSOUTn) + (r - NOUTn)]
                            = acc[r] + g_combb[r];
                }
            }
        }
    }
}

// ---------------- launch ----------------
extern "C" void kernel_launch(void* const* d_in, const int* in_sizes, int n_in,
                              void* d_out, int out_size) {
    const float* stim  = (const float*)d_in[0];
    const float* ctx   = (const float*)d_in[1];
    const float* w_rec = (const float*)d_in[2];
    const float* b_rec = (const float*)d_in[3];
    const float* w_in  = (const float*)d_in[4];
    const float* w_ctx = (const float*)d_in[5];
    const float* w_out = (const float*)d_in[6];
    const float* b_out = (const float*)d_in[7];
    const float* c1_w  = (const float*)d_in[8];
    const float* c1_b  = (const float*)d_in[9];
    const float* c2_w  = (const float*)d_in[10];
    const float* c2_b  = (const float*)d_in[11];
    const float* noise = (const float*)d_in[12];

    float* out0 = (float*)d_out;                         // [B, T, 3]
    float* acts = out0 + (size_t)Bn * Tn * NOUTn;        // [B, T, H]
    float* pout = acts + (size_t)Bn * Tn * Hn;           // [B, T, 3, 8]

    static bool attr_set = false;
    if (!attr_set) {
        cudaFuncSetAttribute(mega_kernel,
                             cudaFuncAttributeMaxDynamicSharedMemorySize,
                             SMEM_BYTES);
        attr_set = true;
    }

    reset_kernel<<<1, 256>>>();
    mega_kernel<<<NCTA, NTHR, SMEM_BYTES>>>(
        stim, ctx, w_rec, b_rec, w_in, w_ctx, w_out, b_out,
        c1_w, c1_b, c2_w, c2_b, noise, out0, acts, pout);
}

// round 12
// speedup vs baseline: 1.0497x; 1.0497x over previous
#include <cuda_runtime.h>
#include <cuda_bf16.h>
#include <cstdint>

// Problem constants
#define Hn 1024
#define Bn 128
#define Tn 400
#define Sn 64
#define Cn 8
#define NOUTn 3
#define NCLSn 3
#define BOTn 2
#define CLSOUTn 8
#define NEXC 819              // int(1024 * 0.8)

#define NCTA 128
#define NTHR 256
#define JPC 8                 // j columns per CTA in phase B
#define KSL 128               // k-slice per CTA in phase A
#define JSL 64                // j-slice per CTA in phase A
#define NKC 8                 // number of k slices

#define ALPHA_N 0.2f
#define DT_SEC 0.02f
#define NZ_SCALE 0.25f        // NOISE_STD / ALPHA_N
#define AX_SLOW ((float)(20.0 / 1500.0))
#define AX_FAST ((float)(20.0 / 200.0))

#define NR (NOUTn + NCLSn * CLSOUTn)   // 27 fused readout rows
#define PR_ROWS 32

// smem word offsets
#define W_PITCH 72            // 64 j + 8 pad (words) -> conflict-free
#define HP_PITCH 136          // 128 b + 8 pad (words) -> conflict-free
#define SM_WHI 0              // 64 * 72 = 4608 words
#define SM_WLO 4608
#define SM_HPHI 9216          // 64 * 136 = 8704 words
#define SM_HPLO 17920
#define SM_COMB 0             // P3 reuses the W/hp space
#define SMEM_WORDS 27648      // max(26624 scan, 27648 comb)
#define SMEM_BYTES (SMEM_WORDS * 4)

// ---------------- device scratch ----------------
__device__ float g_drive[(size_t)Tn * Hn * Bn];        // [t][h][b], noise folded
__device__ unsigned g_hph[2][(Hn / 2) * Bn];           // h_post hi pairs [k/2][b]
__device__ unsigned g_hpl[2][(Hn / 2) * Bn];           // h_post lo pairs [k/2][b]
__device__ float g_part[2][(size_t)NKC * Hn * Bn];     // [par][kc][j][b]
__device__ float g_comb[NR * Hn];
__device__ float g_combb[NR];
__device__ unsigned g_count;                           // phase-transition counter
__device__ unsigned g_kcnt[NKC * 32];                  // partial-ready counts (padded)
__device__ unsigned g_hcnt[NKC * 32];                  // h_post-ready counts (padded)

// ---------------- sync helpers ----------------
__device__ __forceinline__ void red_rel(unsigned* p) {
    asm volatile("red.release.gpu.global.add.u32 [%0], 1;" :: "l"(p) : "memory");
}
__device__ __forceinline__ unsigned ld_rlx(const unsigned* p) {
    unsigned v;
    asm volatile("ld.relaxed.gpu.global.u32 %0, [%1];" : "=r"(v) : "l"(p) : "memory");
    return v;
}
__device__ __forceinline__ void fence_acq() {
    asm volatile("fence.acq_rel.gpu;" ::: "memory");
}
__device__ __forceinline__ void announce(unsigned* p) {
    __syncthreads();
    if (threadIdx.x == 0) red_rel(p);
}

__device__ __forceinline__ void cp_async16(uint32_t saddr, const void* gaddr) {
    asm volatile("cp.async.cg.shared.global [%0], [%1], 16;" :: "r"(saddr), "l"(gaddr));
}
__device__ __forceinline__ void cp_commit() {
    asm volatile("cp.async.commit_group;");
}
template <int N>
__device__ __forceinline__ void cp_wait() {
    asm volatile("cp.async.wait_group %0;" :: "n"(N));
}

__device__ __forceinline__ void gbar(unsigned target) {
    __syncthreads();
    if (threadIdx.x == 0) {
        red_rel(&g_count);
        while (ld_rlx(&g_count) < target) { }
        fence_acq();
    }
    __syncthreads();
}

// bf16 split helpers
__device__ __forceinline__ unsigned pack_pair_hi(float e, float o,
                                                 float& re, float& ro) {
    __nv_bfloat16 he = __float2bfloat16(e);
    __nv_bfloat16 ho = __float2bfloat16(o);
    re = e - __bfloat162float(he);
    ro = o - __bfloat162float(ho);
    return ((unsigned)__bfloat16_as_ushort(ho) << 16) |
           (unsigned)__bfloat16_as_ushort(he);
}
__device__ __forceinline__ unsigned pack_pair(float e, float o) {
    __nv_bfloat16 he = __float2bfloat16(e);
    __nv_bfloat16 ho = __float2bfloat16(o);
    return ((unsigned)__bfloat16_as_ushort(ho) << 16) |
           (unsigned)__bfloat16_as_ushort(he);
}

#define MMA16816(cr, a0_, a1_, a2_, a3_, b0_, b1_)                          \
    asm volatile("mma.sync.aligned.m16n8k16.row.col.f32.bf16.bf16.f32 "     \
        "{%0,%1,%2,%3}, {%4,%5,%6,%7}, {%8,%9}, {%0,%1,%2,%3};"             \
        : "+f"((cr)[0]), "+f"((cr)[1]), "+f"((cr)[2]), "+f"((cr)[3])        \
        : "r"(a0_), "r"(a1_), "r"(a2_), "r"(a3_), "r"(b0_), "r"(b1_))

// ---------------- reset (graph-replay determinism) ----------------
__global__ void reset_kernel() {
    int i = threadIdx.x;
    if (i == 0) g_count = 0;
    if (i < NKC * 32) { g_kcnt[i] = 0; g_hcnt[i] = 0; }
}

// ---------------- the single persistent kernel ----------------
__global__ void __launch_bounds__(NTHR, 1) mega_kernel(
        const float* __restrict__ stim,
        const float* __restrict__ ctx,
        const float* __restrict__ w_rec,
        const float* __restrict__ b_rec,
        const float* __restrict__ w_in,
        const float* __restrict__ w_ctx,
        const float* __restrict__ w_out,
        const float* __restrict__ b_out,
        const float* __restrict__ c1_w,
        const float* __restrict__ c1_b,
        const float* __restrict__ c2_w,
        const float* __restrict__ c2_b,
        const float* __restrict__ noise,
        float* __restrict__ out0,
        float* __restrict__ acts,
        float* __restrict__ pout) {
    extern __shared__ float sm[];
    unsigned* wh  = (unsigned*)(sm + SM_WHI);    // [64 kq][72] pairs
    unsigned* wl  = (unsigned*)(sm + SM_WLO);
    unsigned* hph = (unsigned*)(sm + SM_HPHI);   // [64 kq][136] pairs
    unsigned* hpl = (unsigned*)(sm + SM_HPLO);

    const int c    = blockIdx.x;
    const int tid  = threadIdx.x;
    const int lane = tid & 31;
    const int warp = tid >> 5;            // 0..7 : m-tile (b block 16*warp)
    // phase A roles
    const int kc = c >> 4, jc = c & 15;
    const int kc32 = kc * 32;
    const int la4 = lane & 3, ld4 = lane >> 2;
    const int bb = 16 * warp + ld4;
    // phase B roles
    const int b  = tid & 127;
    const int g  = tid >> 7;              // 0..1
    const int j0 = c * JPC;
    const int jg = j0 + 4 * g;            // 4 columns, jg multiple of 4

    // ---- P0a: classifier fusion ----
    {
        int idx = c * NTHR + tid;
        if (idx < NOUTn * Hn) g_comb[idx] = w_out[idx];
        if (idx < NCLSn * CLSOUTn * Hn) {
            int r = idx / Hn, h = idx % Hn;
            int j = r / CLSOUTn, o = r % CLSOUTn;
            float acc = 0.f;
            #pragma unroll
            for (int k = 0; k < BOTn; k++)
                acc += c2_w[(j * CLSOUTn + o) * BOTn + k] * c1_w[(j * BOTn + k) * Hn + h];
            g_comb[(NOUTn + r) * Hn + h] = acc;
        }
        if (idx < NOUTn) g_combb[idx] = b_out[idx];
        if (idx >= NOUTn && idx < NR) {
            int r = idx - NOUTn;
            int j = r / CLSOUTn, o = r % CLSOUTn;
            float acc = c2_b[j * CLSOUTn + o];
            #pragma unroll
            for (int k = 0; k < BOTn; k++)
                acc += c2_w[(j * CLSOUTn + o) * BOTn + k] * c1_b[j * BOTn + k];
            g_combb[idx] = acc;
        }
    }

    // ---- P0b: W slice as hi/lo bf16 k-pairs ----
    for (int idx = tid; idx < 64 * JSL; idx += NTHR) {
        int kq = idx >> 6, jl = idx & 63;
        int k0 = kc * KSL + 2 * kq, j = jc * JSL + jl;
        float w0 = fmaxf(w_rec[(size_t)k0 * Hn + j], 0.f);
        float w1 = fmaxf(w_rec[(size_t)(k0 + 1) * Hn + j], 0.f);
        if (k0 == j) w0 = 0.f;
        if (k0 + 1 == j) w1 = 0.f;
        w0 = (k0 < NEXC) ? w0 : -w0;
        w1 = (k0 + 1 < NEXC) ? w1 : -w1;
        float r0, r1;
        wh[kq * W_PITCH + jl] = pack_pair_hi(w0, w1, r0, r1);
        wl[kq * W_PITCH + jl] = pack_pair(r0, r1);
    }
    float br[4];
    #pragma unroll
    for (int jj = 0; jj < 4; jj++) br[jj] = b_rec[jg + jj];

    // ---- P0c: initial h_post(0) = 0, announce ----
    {
        int kq0 = jg >> 1;
        g_hph[0][kq0 * Bn + b] = 0u;
        g_hph[0][(kq0 + 1) * Bn + b] = 0u;
        g_hpl[0][kq0 * Bn + b] = 0u;
        g_hpl[0][(kq0 + 1) * Bn + b] = 0u;
    }
    announce(&g_hcnt[kc32]);

    // ---- P1: drive precompute ----
    {
        const int gg = tid >> 7;
        const int bbb = tid & 127;
        for (int u = c; u < Tn * 4; u += NCTA) {
            const int t = u % Tn;
            const int h0 = (u / Tn) * 256 + gg * 128;

            float sin_r[Sn], cin_r[Cn];
            const float4* sp = (const float4*)(stim + ((size_t)bbb * Tn + t) * Sn);
            #pragma unroll
            for (int p = 0; p < Sn / 4; p++) {
                float4 v = sp[p];
                sin_r[4*p] = v.x; sin_r[4*p+1] = v.y; sin_r[4*p+2] = v.z; sin_r[4*p+3] = v.w;
            }
            const float4* cpp = (const float4*)(ctx + ((size_t)bbb * Tn + t) * Cn);
            #pragma unroll
            for (int p = 0; p < Cn / 4; p++) {
                float4 v = cpp[p];
                cin_r[4*p] = v.x; cin_r[4*p+1] = v.y; cin_r[4*p+2] = v.z; cin_r[4*p+3] = v.w;
            }
            const float4* nzp = (const float4*)(noise + ((size_t)t * Bn + bbb) * Hn);

            for (int hh = 0; hh < 128; hh += 4) {
                const int h = h0 + hh;
                float acc0 = 0.f, acc1 = 0.f, acc2 = 0.f, acc3 = 0.f;
                #pragma unroll
                for (int s4 = 0; s4 < Sn / 4; s4++) {
                    float4 w0 = *(const float4*)(w_in + (size_t)(h + 0) * Sn + s4 * 4);
                    float4 w1 = *(const float4*)(w_in + (size_t)(h + 1) * Sn + s4 * 4);
                    float4 w2 = *(const float4*)(w_in + (size_t)(h + 2) * Sn + s4 * 4);
                    float4 w3 = *(const float4*)(w_in + (size_t)(h + 3) * Sn + s4 * 4);
                    float i0 = sin_r[4*s4], i1 = sin_r[4*s4+1];
                    float i2 = sin_r[4*s4+2], i3 = sin_r[4*s4+3];
                    acc0 = fmaf(i0, w0.x, acc0); acc0 = fmaf(i1, w0.y, acc0);
                    acc0 = fmaf(i2, w0.z, acc0); acc0 = fmaf(i3, w0.w, acc0);
                    acc1 = fmaf(i0, w1.x, acc1); acc1 = fmaf(i1, w1.y, acc1);
                    acc1 = fmaf(i2, w1.z, acc1); acc1 = fmaf(i3, w1.w, acc1);
                    acc2 = fmaf(i0, w2.x, acc2); acc2 = fmaf(i1, w2.y, acc2);
                    acc2 = fmaf(i2, w2.z, acc2); acc2 = fmaf(i3, w2.w, acc2);
                    acc3 = fmaf(i0, w3.x, acc3); acc3 = fmaf(i1, w3.y, acc3);
                    acc3 = fmaf(i2, w3.z, acc3); acc3 = fmaf(i3, w3.w, acc3);
                }
                #pragma unroll
                for (int c4 = 0; c4 < Cn / 4; c4++) {
                    float4 w0 = *(const float4*)(w_ctx + (size_t)(h + 0) * Cn + c4 * 4);
                    float4 w1 = *(const float4*)(w_ctx + (size_t)(h + 1) * Cn + c4 * 4);
                    float4 w2 = *(const float4*)(w_ctx + (size_t)(h + 2) * Cn + c4 * 4);
                    float4 w3 = *(const float4*)(w_ctx + (size_t)(h + 3) * Cn + c4 * 4);
                    float i0 = cin_r[4*c4], i1 = cin_r[4*c4+1];
                    float i2 = cin_r[4*c4+2], i3 = cin_r[4*c4+3];
                    acc0 = fmaf(i0, w0.x, acc0); acc0 = fmaf(i1, w0.y, acc0);
                    acc0 = fmaf(i2, w0.z, acc0); acc0 = fmaf(i3, w0.w, acc0);
                    acc1 = fmaf(i0, w1.x, acc1); acc1 = fmaf(i1, w1.y, acc1);
                    acc1 = fmaf(i2, w1.z, acc1); acc1 = fmaf(i3, w1.w, acc1);
                    acc2 = fmaf(i0, w2.x, acc2); acc2 = fmaf(i1, w2.y, acc2);
                    acc2 = fmaf(i2, w2.z, acc2); acc2 = fmaf(i3, w2.w, acc2);
                    acc3 = fmaf(i0, w3.x, acc3); acc3 = fmaf(i1, w3.y, acc3);
                    acc3 = fmaf(i2, w3.z, acc3); acc3 = fmaf(i3, w3.w, acc3);
                }
                float4 nz = nzp[h >> 2];
                float* gd = g_drive + ((size_t)t * Hn + h) * Bn + bbb;
                gd[0]      = fmaf(NZ_SCALE, nz.x, acc0);
                gd[Bn]     = fmaf(NZ_SCALE, nz.y, acc1);
                gd[2 * Bn] = fmaf(NZ_SCALE, nz.z, acc2);
                gd[3 * Bn] = fmaf(NZ_SCALE, nz.w, acc3);
            }
        }
    }

    gbar(NCTA);   // drive complete

    // ---- P2: scan ----
    float h[4], sx[4], su[4];
    #pragma unroll
    for (int jj = 0; jj < 4; jj++) {
        h[jj] = 0.f;
        sx[jj] = 1.f;
        su[jj] = (jj & 1) ? 0.15f : 0.45f;   // jg multiple of 4
    }

    const uint32_t hph_addr = (uint32_t)__cvta_generic_to_shared(hph);
    const uint32_t hpl_addr = (uint32_t)__cvta_generic_to_shared(hpl);

    for (int step = 0; step < Tn; step++) {
        const unsigned stp1 = 16u * (unsigned)(step + 1);
        const int par = step & 1;

        // drive prefetch (overlaps the flag wait)
        const float* gd = g_drive + ((size_t)step * Hn + jg) * Bn + b;
        float d0 = __ldcg(gd), d1 = __ldcg(gd + Bn);
        float d2 = __ldcg(gd + 2 * Bn), d3 = __ldcg(gd + 3 * Bn);

        // ---- wait: h_post pairs for my k-slice ready (relaxed spin + fence) ----
        if (tid == 0) {
            while (ld_rlx(&g_hcnt[kc32]) < stp1) { }
            fence_acq();
        }
        __syncthreads();

        // ---- phase A: stage pairs, group0 = ALL hi, group1 = ALL lo ----
        {
            const unsigned* srch = g_hph[par] + (size_t)(kc * 64) * Bn;
            const unsigned* srcl = g_hpl[par] + (size_t)(kc * 64) * Bn;
            #pragma unroll
            for (int i = 0; i < 8; i++) {
                int id = tid + i * 256;              // 0..2047
                int r = id >> 5, ch = id & 31;       // 64 rows x 32 chunks(16B)
                cp_async16(hph_addr + r * (HP_PITCH * 4) + ch * 16,
                           (const char*)srch + r * 512 + ch * 16);
            }
            cp_commit();
            #pragma unroll
            for (int i = 0; i < 8; i++) {
                int id = tid + i * 256;
                int r = id >> 5, ch = id & 31;
                cp_async16(hpl_addr + r * (HP_PITCH * 4) + ch * 16,
                           (const char*)srcl + r * 512 + ch * 16);
            }
            cp_commit();
        }

        // ---- MMA GEMM: pass 1+2 (hi frags) behind hi group; pass 3 behind lo ----
        float C[8][4];
        #pragma unroll
        for (int nt = 0; nt < 8; nt++) {
            C[nt][0] = 0.f; C[nt][1] = 0.f; C[nt][2] = 0.f; C[nt][3] = 0.f;
        }

        cp_wait<1>();
        __syncthreads();
        #pragma unroll
        for (int t = 0; t < 8; t++) {
            const int kq = 8 * t + la4;
            unsigned ah0 = hph[kq * HP_PITCH + bb];
            unsigned ah1 = hph[kq * HP_PITCH + bb + 8];
            unsigned ah2 = hph[(kq + 4) * HP_PITCH + bb];
            unsigned ah3 = hph[(kq + 4) * HP_PITCH + bb + 8];
            #pragma unroll
            for (int nt = 0; nt < 8; nt++) {
                int jo = 8 * nt + ld4;
                unsigned bh0 = wh[kq * W_PITCH + jo];
                unsigned bh1 = wh[(kq + 4) * W_PITCH + jo];
                unsigned bl0 = wl[kq * W_PITCH + jo];
                unsigned bl1 = wl[(kq + 4) * W_PITCH + jo];
                MMA16816(C[nt], ah0, ah1, ah2, ah3, bh0, bh1);
                MMA16816(C[nt], ah0, ah1, ah2, ah3, bl0, bl1);
            }
        }

        cp_wait<0>();
        __syncthreads();
        #pragma unroll
        for (int t = 0; t < 8; t++) {
            const int kq = 8 * t + la4;
            unsigned al0 = hpl[kq * HP_PITCH + bb];
            unsigned al1 = hpl[kq * HP_PITCH + bb + 8];
            unsigned al2 = hpl[(kq + 4) * HP_PITCH + bb];
            unsigned al3 = hpl[(kq + 4) * HP_PITCH + bb + 8];
            #pragma unroll
            for (int nt = 0; nt < 8; nt++) {
                int jo = 8 * nt + ld4;
                unsigned bh0 = wh[kq * W_PITCH + jo];
                unsigned bh1 = wh[(kq + 4) * W_PITCH + jo];
                MMA16816(C[nt], al0, al1, al2, al3, bh0, bh1);
            }
        }

        // write partials [kc][j][b]
        {
            float* gpart = g_part[par];
            #pragma unroll
            for (int nt = 0; nt < 8; nt++) {
                int j = jc * JSL + 8 * nt + 2 * la4;
                float* p0 = gpart + ((size_t)kc * Hn + j) * Bn;
                p0[bb]          = C[nt][0];
                p0[Bn + bb]     = C[nt][1];
                p0[bb + 8]      = C[nt][2];
                p0[Bn + bb + 8] = C[nt][3];
            }
        }

        announce(&g_kcnt[kc32]);

        // ---- phase B: wait all 8 partial groups (relaxed spins, MLP=8) ----
        if (tid == 0) {
            for (;;) {
                unsigned ok = 1;
                #pragma unroll
                for (int k2 = 0; k2 < NKC; k2++)
                    ok &= (ld_rlx(&g_kcnt[k2 * 32]) >= stp1) ? 1u : 0u;
                if (ok) break;
            }
            fence_acq();
        }
        __syncthreads();

        float s0 = 0.f, s1 = 0.f, s2 = 0.f, s3 = 0.f;
        {
            const float* gpart = g_part[par];
            #pragma unroll
            for (int k2 = 0; k2 < NKC; k2++) {
                const float* pp = gpart + ((size_t)k2 * Hn + jg) * Bn + b;
                s0 += __ldcg(pp);
                s1 += __ldcg(pp + Bn);
                s2 += __ldcg(pp + 2 * Bn);
                s3 += __ldcg(pp + 3 * Bn);
            }
        }
        float ss[4] = {s0, s1, s2, s3};
        float dd[4] = {d0, d1, d2, d3};
        float hn[4], hp[4];
        #pragma unroll
        for (int jj = 0; jj < 4; jj++) {
            float val = h[jj] * (1.f - ALPHA_N)
                      + ALPHA_N * (dd[jj] + ss[jj] + br[jj]);
            hn[jj] = fmaxf(val, 0.f);
            h[jj] = hn[jj];
        }
        // STP + h_post(step+1) pairs, announce, then acts store
        #pragma unroll
        for (int jj = 0; jj < 4; jj++) {
            const float axv = (jj & 1) ? AX_FAST : AX_SLOW;
            const float Uv  = (jj & 1) ? 0.15f : 0.45f;
            float hh = h[jj];
            float sxo = sx[jj], suo = su[jj];
            float sxn = sxo + axv * (1.f - sxo) - DT_SEC * suo * sxo * hh;
            float sun = suo + axv * (Uv - suo) + DT_SEC * Uv * (1.f - suo) * hh;
            sxn = fminf(fmaxf(sxn, 0.f), 1.f);
            sun = fminf(fmaxf(sun, 0.f), 1.f);
            sx[jj] = sxn; su[jj] = sun;
            hp[jj] = sun * sxn * hh;
        }
        {
            unsigned* dh = g_hph[par ^ 1];
            unsigned* dl = g_hpl[par ^ 1];
            int kq0 = jg >> 1;
            float r0, r1, r2, r3;
            unsigned h01 = pack_pair_hi(hp[0], hp[1], r0, r1);
            unsigned h23 = pack_pair_hi(hp[2], hp[3], r2, r3);
            dh[kq0 * Bn + b]       = h01;
            dh[(kq0 + 1) * Bn + b] = h23;
            dl[kq0 * Bn + b]       = pack_pair(r0, r1);
            dl[(kq0 + 1) * Bn + b] = pack_pair(r2, r3);
        }
        announce(&g_hcnt[kc32]);

        *(float4*)(acts + ((size_t)b * Tn + step) * Hn + jg) =
            make_float4(hn[0], hn[1], hn[2], hn[3]);
    }

    gbar(2 * NCTA);   // scan complete

    // ---- P3: post (fused readout) ----
    {
        float* s_comb = sm + SM_COMB;
        for (int i = tid; i < NR * Hn; i += NTHR) s_comb[i] = g_comb[i];
        __syncthreads();

        const float4* comb4 = (const float4*)s_comb;

        for (int u = c; u < (Bn * Tn) / PR_ROWS; u += NCTA) {
            #pragma unroll 1
            for (int rr = 0; rr < 4; rr++) {
                const int bt = u * PR_ROWS + warp * 4 + rr;
                const float4* a4 = (const float4*)(acts + (size_t)bt * Hn);

                float acc[NR];
                #pragma unroll
                for (int r = 0; r < NR; r++) acc[r] = 0.f;

                #pragma unroll
                for (int it = 0; it < Hn / 128; it++) {
                    float4 a = a4[it * 32 + lane];
                    #pragma unroll
                    for (int r = 0; r < NR; r++) {
                        float4 ww = comb4[r * 256 + it * 32 + lane];
                        float s = a.x * ww.x + a.y * ww.y;
                        s = fmaf(a.z, ww.z, s);
                        s = fmaf(a.w, ww.w, s);
                        acc[r] += s;
                    }
                }
                #pragma unroll
                for (int r = 0; r < NR; r++) {
                    #pragma unroll
                    for (int off = 16; off > 0; off >>= 1)
                        acc[r] += __shfl_down_sync(0xffffffffu, acc[r], off);
                }
                if (lane == 0) {
                    #pragma unroll
                    for (int r = 0; r < NOUTn; r++)
                        out0[(size_t)bt * NOUTn + r] = acc[r] + g_combb[r];
                    #pragma unroll
                    for (int r = NOUTn; r < NR; r++)
                        pout[(size_t)bt * (NCLSn * CLSOUTn) + (r - NOUTn)]
                            = acc[r] + g_combb[r];
                }
            }
        }
    }
}

// ---------------- launch ----------------
extern "C" void kernel_launch(void* const* d_in, const int* in_sizes, int n_in,
                              void* d_out, int out_size) {
    const float* stim  = (const float*)d_in[0];
    const float* ctx   = (const float*)d_in[1];
    const float* w_rec = (const float*)d_in[2];
    const float* b_rec = (const float*)d_in[3];
    const float* w_in  = (const float*)d_in[4];
    const float* w_ctx = (const float*)d_in[5];
    const float* w_out = (const float*)d_in[6];
    const float* b_out = (const float*)d_in[7];
    const float* c1_w  = (const float*)d_in[8];
    const float* c1_b  = (const float*)d_in[9];
    const float* c2_w  = (const float*)d_in[10];
    const float* c2_b  = (const float*)d_in[11];
    const float* noise = (const float*)d_in[12];

    float* out0 = (float*)d_out;                         // [B, T, 3]
    float* acts = out0 + (size_t)Bn * Tn * NOUTn;        // [B, T, H]
    float* pout = acts + (size_t)Bn * Tn * Hn;           // [B, T, 3, 8]

    static bool attr_set = false;
    if (!attr_set) {
        cudaFuncSetAttribute(mega_kernel,
                             cudaFuncAttributeMaxDynamicSharedMemorySize,
                             SMEM_BYTES);
        attr_set = true;
    }

    reset_kernel<<<1, 256>>>();
    mega_kernel<<<NCTA, NTHR, SMEM_BYTES>>>(
        stim, ctx, w_rec, b_rec, w_in, w_ctx, w_out, b_out,
        c1_w, c1_b, c2_w, c2_b, noise, out0, acts, pout);
}

// round 15
// speedup vs baseline: 1.0559x; 1.0059x over previous
#include <cuda_runtime.h>
#include <cuda_bf16.h>
#include <cstdint>

// Problem constants
#define Hn 1024
#define Bn 128
#define Tn 400
#define Sn 64
#define Cn 8
#define NOUTn 3
#define NCLSn 3
#define BOTn 2
#define CLSOUTn 8
#define NEXC 819              // int(1024 * 0.8)

#define NCTA 128
#define NTHR 256
#define JPC 8                 // j columns per CTA in phase B
#define KSL 128               // k-slice per CTA in phase A
#define JSL 64                // j-slice per CTA in phase A
#define NKC 8                 // number of k slices
#define NJC 16                // number of j slices

#define ALPHA_N 0.2f
#define DT_SEC 0.02f
#define NZ_SCALE 0.25f        // NOISE_STD / ALPHA_N
#define AX_SLOW ((float)(20.0 / 1500.0))
#define AX_FAST ((float)(20.0 / 200.0))

#define NR (NOUTn + NCLSn * CLSOUTn)   // 27 fused readout rows
#define PR_ROWS 32

// smem word offsets
#define W_PITCH 72            // 64 j + 8 pad (words) -> conflict-free
#define HP_PITCH 136          // 128 b + 8 pad (words) -> conflict-free
#define SM_WHI 0              // 64 * 72 = 4608 words
#define SM_WLO 4608
#define SM_HPHI 9216          // 64 * 136 = 8704 words
#define SM_HPLO 17920
#define SM_COMB 0             // P3 reuses the W/hp space
#define SMEM_WORDS 27648      // max(26624 scan, 27648 comb)
#define SMEM_BYTES (SMEM_WORDS * 4)

// ---------------- device scratch ----------------
__device__ float g_drive[(size_t)Tn * Hn * Bn];        // [t][h][b], noise folded
__device__ unsigned g_hph[2][(Hn / 2) * Bn];           // h_post hi pairs [k/2][b]
__device__ unsigned g_hpl[2][(Hn / 2) * Bn];           // h_post lo pairs [k/2][b]
__device__ float g_part[2][(size_t)NKC * Hn * Bn];     // [par][kc][j][b]
__device__ float g_comb[NR * Hn];
__device__ float g_combb[NR];
__device__ unsigned g_count;                           // phase-transition counter
__device__ unsigned g_jcnt[NJC * 32];                  // partial-ready per j-slice (8/step)
__device__ unsigned g_rdone[NJC * 32];                 // partial-READ-done per j-slice (8/step)
__device__ unsigned g_hcnt[NKC * 32];                  // h_post-ready per k-slice (16/step)

// ---------------- sync helpers ----------------
__device__ __forceinline__ void red_rel(unsigned* p) {
    asm volatile("red.release.gpu.global.add.u32 [%0], 1;" :: "l"(p) : "memory");
}
__device__ __forceinline__ unsigned ld_rlx(const unsigned* p) {
    unsigned v;
    asm volatile("ld.relaxed.gpu.global.u32 %0, [%1];" : "=r"(v) : "l"(p) : "memory");
    return v;
}
__device__ __forceinline__ void fence_acq() {
    asm volatile("fence.acq_rel.gpu;" ::: "memory");
}
__device__ __forceinline__ void announce(unsigned* p) {
    __syncthreads();
    if (threadIdx.x == 0) red_rel(p);
}

__device__ __forceinline__ void cp_async16(uint32_t saddr, const void* gaddr) {
    asm volatile("cp.async.cg.shared.global [%0], [%1], 16;" :: "r"(saddr), "l"(gaddr));
}
__device__ __forceinline__ void cp_commit() {
    asm volatile("cp.async.commit_group;");
}
template <int N>
__device__ __forceinline__ void cp_wait() {
    asm volatile("cp.async.wait_group %0;" :: "n"(N));
}

__device__ __forceinline__ void gbar(unsigned target) {
    __syncthreads();
    if (threadIdx.x == 0) {
        red_rel(&g_count);
        while (ld_rlx(&g_count) < target) { }
        fence_acq();
    }
    __syncthreads();
}

// bf16 split helpers
__device__ __forceinline__ unsigned pack_pair_hi(float e, float o,
                                                 float& re, float& ro) {
    __nv_bfloat16 he = __float2bfloat16(e);
    __nv_bfloat16 ho = __float2bfloat16(o);
    re = e - __bfloat162float(he);
    ro = o - __bfloat162float(ho);
    return ((unsigned)__bfloat16_as_ushort(ho) << 16) |
           (unsigned)__bfloat16_as_ushort(he);
}
__device__ __forceinline__ unsigned pack_pair(float e, float o) {
    __nv_bfloat16 he = __float2bfloat16(e);
    __nv_bfloat16 ho = __float2bfloat16(o);
    return ((unsigned)__bfloat16_as_ushort(ho) << 16) |
           (unsigned)__bfloat16_as_ushort(he);
}

#define MMA16816(cr, a0_, a1_, a2_, a3_, b0_, b1_)                          \
    asm volatile("mma.sync.aligned.m16n8k16.row.col.f32.bf16.bf16.f32 "     \
        "{%0,%1,%2,%3}, {%4,%5,%6,%7}, {%8,%9}, {%0,%1,%2,%3};"             \
        : "+f"((cr)[0]), "+f"((cr)[1]), "+f"((cr)[2]), "+f"((cr)[3])        \
        : "r"(a0_), "r"(a1_), "r"(a2_), "r"(a3_), "r"(b0_), "r"(b1_))

// ---------------- reset (graph-replay determinism) ----------------
// 512 threads: must cover ALL flag words (NJC*32 = 512). A short reset was
// the R13/R14 divergence bug: j-slices 8..15 kept stale counters across
// graph replays, letting waits pass instantly on replay.
__global__ void reset_kernel() {
    int i = threadIdx.x;
    if (i == 0) g_count = 0;
    if (i < NJC * 32) { g_jcnt[i] = 0; g_rdone[i] = 0; }
    if (i < NKC * 32) g_hcnt[i] = 0;
}

// ---------------- the single persistent kernel ----------------
__global__ void __launch_bounds__(NTHR, 1) mega_kernel(
        const float* __restrict__ stim,
        const float* __restrict__ ctx,
        const float* __restrict__ w_rec,
        const float* __restrict__ b_rec,
        const float* __restrict__ w_in,
        const float* __restrict__ w_ctx,
        const float* __restrict__ w_out,
        const float* __restrict__ b_out,
        const float* __restrict__ c1_w,
        const float* __restrict__ c1_b,
        const float* __restrict__ c2_w,
        const float* __restrict__ c2_b,
        const float* __restrict__ noise,
        float* __restrict__ out0,
        float* __restrict__ acts,
        float* __restrict__ pout) {
    extern __shared__ float sm[];
    unsigned* wh  = (unsigned*)(sm + SM_WHI);    // [64 kq][72] pairs
    unsigned* wl  = (unsigned*)(sm + SM_WLO);
    unsigned* hph = (unsigned*)(sm + SM_HPHI);   // [64 kq][136] pairs
    unsigned* hpl = (unsigned*)(sm + SM_HPLO);

    const int c    = blockIdx.x;
    const int tid  = threadIdx.x;
    const int lane = tid & 31;
    const int warp = tid >> 5;            // 0..7 : m-tile (b block 16*warp)
    // phase A roles
    const int kc = c >> 4, jc = c & 15;
    const int kc32 = kc * 32;
    const int jc32 = jc * 32;
    const int la4 = lane & 3, ld4 = lane >> 2;
    const int bb = 16 * warp + ld4;
    // phase B roles
    const int b  = tid & 127;
    const int g  = tid >> 7;              // 0..1
    const int j0 = c * JPC;
    const int jg = j0 + 4 * g;            // 4 columns, jg multiple of 4
    const int myjc32 = (c >> 3) * 32;     // j-slice containing my 8 columns

    // ---- P0a: classifier fusion ----
    {
        int idx = c * NTHR + tid;
        if (idx < NOUTn * Hn) g_comb[idx] = w_out[idx];
        if (idx < NCLSn * CLSOUTn * Hn) {
            int r = idx / Hn, h = idx % Hn;
            int j = r / CLSOUTn, o = r % CLSOUTn;
            float acc = 0.f;
            #pragma unroll
            for (int k = 0; k < BOTn; k++)
                acc += c2_w[(j * CLSOUTn + o) * BOTn + k] * c1_w[(j * BOTn + k) * Hn + h];
            g_comb[(NOUTn + r) * Hn + h] = acc;
        }
        if (idx < NOUTn) g_combb[idx] = b_out[idx];
        if (idx >= NOUTn && idx < NR) {
            int r = idx - NOUTn;
            int j = r / CLSOUTn, o = r % CLSOUTn;
            float acc = c2_b[j * CLSOUTn + o];
            #pragma unroll
            for (int k = 0; k < BOTn; k++)
                acc += c2_w[(j * CLSOUTn + o) * BOTn + k] * c1_b[j * BOTn + k];
            g_combb[idx] = acc;
        }
    }

    // ---- P0b: W slice as hi/lo bf16 k-pairs ----
    for (int idx = tid; idx < 64 * JSL; idx += NTHR) {
        int kq = idx >> 6, jl = idx & 63;
        int k0 = kc * KSL + 2 * kq, j = jc * JSL + jl;
        float w0 = fmaxf(w_rec[(size_t)k0 * Hn + j], 0.f);
        float w1 = fmaxf(w_rec[(size_t)(k0 + 1) * Hn + j], 0.f);
        if (k0 == j) w0 = 0.f;
        if (k0 + 1 == j) w1 = 0.f;
        w0 = (k0 < NEXC) ? w0 : -w0;
        w1 = (k0 + 1 < NEXC) ? w1 : -w1;
        float r0, r1;
        wh[kq * W_PITCH + jl] = pack_pair_hi(w0, w1, r0, r1);
        wl[kq * W_PITCH + jl] = pack_pair(r0, r1);
    }
    float br[4];
    #pragma unroll
    for (int jj = 0; jj < 4; jj++) br[jj] = b_rec[jg + jj];

    // ---- P0c: initial h_post(0) = 0, announce ----
    {
        int kq0 = jg >> 1;
        g_hph[0][kq0 * Bn + b] = 0u;
        g_hph[0][(kq0 + 1) * Bn + b] = 0u;
        g_hpl[0][kq0 * Bn + b] = 0u;
        g_hpl[0][(kq0 + 1) * Bn + b] = 0u;
    }
    announce(&g_hcnt[kc32]);

    // ---- P1: drive precompute ----
    {
        const int gg = tid >> 7;
        const int bbb = tid & 127;
        for (int u = c; u < Tn * 4; u += NCTA) {
            const int t = u % Tn;
            const int h0 = (u / Tn) * 256 + gg * 128;

            float sin_r[Sn], cin_r[Cn];
            const float4* sp = (const float4*)(stim + ((size_t)bbb * Tn + t) * Sn);
            #pragma unroll
            for (int p = 0; p < Sn / 4; p++) {
                float4 v = sp[p];
                sin_r[4*p] = v.x; sin_r[4*p+1] = v.y; sin_r[4*p+2] = v.z; sin_r[4*p+3] = v.w;
            }
            const float4* cpp = (const float4*)(ctx + ((size_t)bbb * Tn + t) * Cn);
            #pragma unroll
            for (int p = 0; p < Cn / 4; p++) {
                float4 v = cpp[p];
                cin_r[4*p] = v.x; cin_r[4*p+1] = v.y; cin_r[4*p+2] = v.z; cin_r[4*p+3] = v.w;
            }
            const float4* nzp = (const float4*)(noise + ((size_t)t * Bn + bbb) * Hn);

            for (int hh = 0; hh < 128; hh += 4) {
                const int h = h0 + hh;
                float acc0 = 0.f, acc1 = 0.f, acc2 = 0.f, acc3 = 0.f;
                #pragma unroll
                for (int s4 = 0; s4 < Sn / 4; s4++) {
                    float4 w0 = *(const float4*)(w_in + (size_t)(h + 0) * Sn + s4 * 4);
                    float4 w1 = *(const float4*)(w_in + (size_t)(h + 1) * Sn + s4 * 4);
                    float4 w2 = *(const float4*)(w_in + (size_t)(h + 2) * Sn + s4 * 4);
                    float4 w3 = *(const float4*)(w_in + (size_t)(h + 3) * Sn + s4 * 4);
                    float i0 = sin_r[4*s4], i1 = sin_r[4*s4+1];
                    float i2 = sin_r[4*s4+2], i3 = sin_r[4*s4+3];
                    acc0 = fmaf(i0, w0.x, acc0); acc0 = fmaf(i1, w0.y, acc0);
                    acc0 = fmaf(i2, w0.z, acc0); acc0 = fmaf(i3, w0.w, acc0);
                    acc1 = fmaf(i0, w1.x, acc1); acc1 = fmaf(i1, w1.y, acc1);
                    acc1 = fmaf(i2, w1.z, acc1); acc1 = fmaf(i3, w1.w, acc1);
                    acc2 = fmaf(i0, w2.x, acc2); acc2 = fmaf(i1, w2.y, acc2);
                    acc2 = fmaf(i2, w2.z, acc2); acc2 = fmaf(i3, w2.w, acc2);
                    acc3 = fmaf(i0, w3.x, acc3); acc3 = fmaf(i1, w3.y, acc3);
                    acc3 = fmaf(i2, w3.z, acc3); acc3 = fmaf(i3, w3.w, acc3);
                }
                #pragma unroll
                for (int c4 = 0; c4 < Cn / 4; c4++) {
                    float4 w0 = *(const float4*)(w_ctx + (size_t)(h + 0) * Cn + c4 * 4);
                    float4 w1 = *(const float4*)(w_ctx + (size_t)(h + 1) * Cn + c4 * 4);
                    float4 w2 = *(const float4*)(w_ctx + (size_t)(h + 2) * Cn + c4 * 4);
                    float4 w3 = *(const float4*)(w_ctx + (size_t)(h + 3) * Cn + c4 * 4);
                    float i0 = cin_r[4*c4], i1 = cin_r[4*c4+1];
                    float i2 = cin_r[4*c4+2], i3 = cin_r[4*c4+3];
                    acc0 = fmaf(i0, w0.x, acc0); acc0 = fmaf(i1, w0.y, acc0);
                    acc0 = fmaf(i2, w0.z, acc0); acc0 = fmaf(i3, w0.w, acc0);
                    acc1 = fmaf(i0, w1.x, acc1); acc1 = fmaf(i1, w1.y, acc1);
                    acc1 = fmaf(i2, w1.z, acc1); acc1 = fmaf(i3, w1.w, acc1);
                    acc2 = fmaf(i0, w2.x, acc2); acc2 = fmaf(i1, w2.y, acc2);
                    acc2 = fmaf(i2, w2.z, acc2); acc2 = fmaf(i3, w2.w, acc2);
                    acc3 = fmaf(i0, w3.x, acc3); acc3 = fmaf(i1, w3.y, acc3);
                    acc3 = fmaf(i2, w3.z, acc3); acc3 = fmaf(i3, w3.w, acc3);
                }
                float4 nz = nzp[h >> 2];
                float* gd = g_drive + ((size_t)t * Hn + h) * Bn + bbb;
                gd[0]      = fmaf(NZ_SCALE, nz.x, acc0);
                gd[Bn]     = fmaf(NZ_SCALE, nz.y, acc1);
                gd[2 * Bn] = fmaf(NZ_SCALE, nz.z, acc2);
                gd[3 * Bn] = fmaf(NZ_SCALE, nz.w, acc3);
            }
        }
    }

    gbar(NCTA);   // drive complete

    // ---- P2: scan ----
    float h[4], sx[4], su[4];
    #pragma unroll
    for (int jj = 0; jj < 4; jj++) {
        h[jj] = 0.f;
        sx[jj] = 1.f;
        su[jj] = (jj & 1) ? 0.15f : 0.45f;   // jg multiple of 4
    }

    const uint32_t hph_addr = (uint32_t)__cvta_generic_to_shared(hph);
    const uint32_t hpl_addr = (uint32_t)__cvta_generic_to_shared(hpl);

    for (int step = 0; step < Tn; step++) {
        const unsigned hp_target = 16u * (unsigned)(step + 1);
        const unsigned pj_target = 8u * (unsigned)(step + 1);
        const unsigned rd_target = (step >= 2) ? 8u * (unsigned)(step - 1) : 0u;
        const int par = step & 1;

        // drive prefetch (overlaps the flag wait)
        const float* gd = g_drive + ((size_t)step * Hn + jg) * Bn + b;
        float d0 = __ldcg(gd), d1 = __ldcg(gd + Bn);
        float d2 = __ldcg(gd + 2 * Bn), d3 = __ldcg(gd + 3 * Bn);

        // ---- wait: h_post ready (RAW) AND readers of my partial slice done (WAR) ----
        if (tid == 0) {
            for (;;) {
                unsigned okh = (ld_rlx(&g_hcnt[kc32]) >= hp_target) ? 1u : 0u;
                unsigned okr = (ld_rlx(&g_rdone[jc32]) >= rd_target) ? 1u : 0u;
                if (okh & okr) break;
            }
            fence_acq();
        }
        __syncthreads();

        // ---- phase A: stage hi/lo pair arrays, 2 pipelined stages ----
        {
            const unsigned* srch = g_hph[par] + (size_t)(kc * 64) * Bn;
            const unsigned* srcl = g_hpl[par] + (size_t)(kc * 64) * Bn;
            #pragma unroll
            for (int s = 0; s < 2; s++) {
                int rb = 32 * s;
                #pragma unroll
                for (int i = 0; i < 4; i++) {
                    int id = tid + i * 256;
                    int r = rb + (id >> 5), ch = id & 31;
                    cp_async16(hph_addr + r * (HP_PITCH * 4) + ch * 16,
                               (const char*)srch + r * 512 + ch * 16);
                }
                #pragma unroll
                for (int i = 0; i < 4; i++) {
                    int id = tid + i * 256;
                    int r = rb + (id >> 5), ch = id & 31;
                    cp_async16(hpl_addr + r * (HP_PITCH * 4) + ch * 16,
                               (const char*)srcl + r * 512 + ch * 16);
                }
                cp_commit();
            }
        }

        // ---- MMA GEMM: C[b 16-tile][j 8-tiles] over k=128 ----
        float C[8][4];
        #pragma unroll
        for (int nt = 0; nt < 8; nt++) {
            C[nt][0] = 0.f; C[nt][1] = 0.f; C[nt][2] = 0.f; C[nt][3] = 0.f;
        }

        #pragma unroll
        for (int t = 0; t < 8; t++) {
            if (t == 0) { cp_wait<1>(); __syncthreads(); }
            if (t == 4) { cp_wait<0>(); __syncthreads(); }
            const int kq = 8 * t + la4;
            unsigned ah0 = hph[kq * HP_PITCH + bb];
            unsigned ah1 = hph[kq * HP_PITCH + bb + 8];
            unsigned ah2 = hph[(kq + 4) * HP_PITCH + bb];
            unsigned ah3 = hph[(kq + 4) * HP_PITCH + bb + 8];
            unsigned al0 = hpl[kq * HP_PITCH + bb];
            unsigned al1 = hpl[kq * HP_PITCH + bb + 8];
            unsigned al2 = hpl[(kq + 4) * HP_PITCH + bb];
            unsigned al3 = hpl[(kq + 4) * HP_PITCH + bb + 8];
            #pragma unroll
            for (int nt = 0; nt < 8; nt++) {
                int jo = 8 * nt + ld4;
                unsigned bh0 = wh[kq * W_PITCH + jo];
                unsigned bh1 = wh[(kq + 4) * W_PITCH + jo];
                unsigned bl0 = wl[kq * W_PITCH + jo];
                unsigned bl1 = wl[(kq + 4) * W_PITCH + jo];
                MMA16816(C[nt], ah0, ah1, ah2, ah3, bh0, bh1);
                MMA16816(C[nt], ah0, ah1, ah2, ah3, bl0, bl1);
                MMA16816(C[nt], al0, al1, al2, al3, bh0, bh1);
            }
        }

        // write partials [kc][j][b]
        {
            float* gpart = g_part[par];
            #pragma unroll
            for (int nt = 0; nt < 8; nt++) {
                int j = jc * JSL + 8 * nt + 2 * la4;
                float* p0 = gpart + ((size_t)kc * Hn + j) * Bn;
                p0[bb]          = C[nt][0];
                p0[Bn + bb]     = C[nt][1];
                p0[bb + 8]      = C[nt][2];
                p0[Bn + bb + 8] = C[nt][3];
            }
        }

        // announce per j-slice: g_jcnt[jc] counts 8 arrivals (one per kc) per step
        announce(&g_jcnt[jc32]);

        // ---- phase B: wait ONLY the 8 producers of my j-slice ----
        if (tid == 0) {
            while (ld_rlx(&g_jcnt[myjc32]) < pj_target) { }
            fence_acq();
        }
        __syncthreads();

        float s0 = 0.f, s1 = 0.f, s2 = 0.f, s3 = 0.f;
        {
            const float* gpart = g_part[par];
            #pragma unroll
            for (int k2 = 0; k2 < NKC; k2++) {
                const float* pp = gpart + ((size_t)k2 * Hn + jg) * Bn + b;
                s0 += __ldcg(pp);
                s1 += __ldcg(pp + Bn);
                s2 += __ldcg(pp + 2 * Bn);
                s3 += __ldcg(pp + 3 * Bn);
            }
        }
        // release: reads of my j-slice's partials are complete (WAR edge)
        announce(&g_rdone[myjc32]);

        float ss[4] = {s0, s1, s2, s3};
        float dd[4] = {d0, d1, d2, d3};
        float hn[4], hp[4];
        #pragma unroll
        for (int jj = 0; jj < 4; jj++) {
            float val = h[jj] * (1.f - ALPHA_N)
                      + ALPHA_N * (dd[jj] + ss[jj] + br[jj]);
            hn[jj] = fmaxf(val, 0.f);
            h[jj] = hn[jj];
        }
        // STP + h_post(step+1) pairs, announce, then acts store
        #pragma unroll
        for (int jj = 0; jj < 4; jj++) {
            const float axv = (jj & 1) ? AX_FAST : AX_SLOW;
            const float Uv  = (jj & 1) ? 0.15f : 0.45f;
            float hh = h[jj];
            float sxo = sx[jj], suo = su[jj];
            float sxn = sxo + axv * (1.f - sxo) - DT_SEC * suo * sxo * hh;
            float sun = suo + axv * (Uv - suo) + DT_SEC * Uv * (1.f - suo) * hh;
            sxn = fminf(fmaxf(sxn, 0.f), 1.f);
            sun = fminf(fmaxf(sun, 0.f), 1.f);
            sx[jj] = sxn; su[jj] = sun;
            hp[jj] = sun * sxn * hh;
        }
        {
            unsigned* dh = g_hph[par ^ 1];
            unsigned* dl = g_hpl[par ^ 1];
            int kq0 = jg >> 1;
            float r0, r1, r2, r3;
            unsigned h01 = pack_pair_hi(hp[0], hp[1], r0, r1);
            unsigned h23 = pack_pair_hi(hp[2], hp[3], r2, r3);
            dh[kq0 * Bn + b]       = h01;
            dh[(kq0 + 1) * Bn + b] = h23;
            dl[kq0 * Bn + b]       = pack_pair(r0, r1);
            dl[(kq0 + 1) * Bn + b] = pack_pair(r2, r3);
        }
        announce(&g_hcnt[kc32]);

        *(float4*)(acts + ((size_t)b * Tn + step) * Hn + jg) =
            make_float4(hn[0], hn[1], hn[2], hn[3]);
    }

    gbar(2 * NCTA);   // scan complete

    // ---- P3: post (fused readout) ----
    {
        float* s_comb = sm + SM_COMB;
        for (int i = tid; i < NR * Hn; i += NTHR) s_comb[i] = g_comb[i];
        __syncthreads();

        const float4* comb4 = (const float4*)s_comb;

        for (int u = c; u < (Bn * Tn) / PR_ROWS; u += NCTA) {
            #pragma unroll 1
            for (int rr = 0; rr < 4; rr++) {
                const int bt = u * PR_ROWS + warp * 4 + rr;
                const float4* a4 = (const float4*)(acts + (size_t)bt * Hn);

                float acc[NR];
                #pragma unroll
                for (int r = 0; r < NR; r++) acc[r] = 0.f;

                #pragma unroll
                for (int it = 0; it < Hn / 128; it++) {
                    float4 a = a4[it * 32 + lane];
                    #pragma unroll
                    for (int r = 0; r < NR; r++) {
                        float4 ww = comb4[r * 256 + it * 32 + lane];
                        float s = a.x * ww.x + a.y * ww.y;
                        s = fmaf(a.z, ww.z, s);
                        s = fmaf(a.w, ww.w, s);
                        acc[r] += s;
                    }
                }
                #pragma unroll
                for (int r = 0; r < NR; r++) {
                    #pragma unroll
                    for (int off = 16; off > 0; off >>= 1)
                        acc[r] += __shfl_down_sync(0xffffffffu, acc[r], off);
                }
                if (lane == 0) {
                    #pragma unroll
                    for (int r = 0; r < NOUTn; r++)
                        out0[(size_t)bt * NOUTn + r] = acc[r] + g_combb[r];
                    #pragma unroll
                    for (int r = NOUTn; r < NR; r++)
                        pout[(size_t)bt * (NCLSn * CLSOUTn) + (r - NOUTn)]
                            = acc[r] + g_combb[r];
                }
            }
        }
    }
}

// ---------------- launch ----------------
extern "C" void kernel_launch(void* const* d_in, const int* in_sizes, int n_in,
                              void* d_out, int out_size) {
    const float* stim  = (const float*)d_in[0];
    const float* ctx   = (const float*)d_in[1];
    const float* w_rec = (const float*)d_in[2];
    const float* b_rec = (const float*)d_in[3];
    const float* w_in  = (const float*)d_in[4];
    const float* w_ctx = (const float*)d_in[5];
    const float* w_out = (const float*)d_in[6];
    const float* b_out = (const float*)d_in[7];
    const float* c1_w  = (const float*)d_in[8];
    const float* c1_b  = (const float*)d_in[9];
    const float* c2_w  = (const float*)d_in[10];
    const float* c2_b  = (const float*)d_in[11];
    const float* noise = (const float*)d_in[12];

    float* out0 = (float*)d_out;                         // [B, T, 3]
    float* acts = out0 + (size_t)Bn * Tn * NOUTn;        // [B, T, H]
    float* pout = acts + (size_t)Bn * Tn * Hn;           // [B, T, 3, 8]

    static bool attr_set = false;
    if (!attr_set) {
        cudaFuncSetAttribute(mega_kernel,
                             cudaFuncAttributeMaxDynamicSharedMemorySize,
                             SMEM_BYTES);
        attr_set = true;
    }

    reset_kernel<<<1, NJC * 32>>>();   // 512 threads: covers every flag word
    mega_kernel<<<NCTA, NTHR, SMEM_BYTES>>>(
        stim, ctx, w_rec, b_rec, w_in, w_ctx, w_out, b_out,
        c1_w, c1_b, c2_w, c2_b, noise, out0, acts, pout);
}

// round 16
// speedup vs baseline: 1.3340x; 1.2633x over previous
#include <cuda_runtime.h>
#include <cuda_bf16.h>
#include <cstdint>

// Problem constants
#define Hn 1024
#define Bn 128
#define Tn 400
#define Sn 64
#define Cn 8
#define NOUTn 3
#define NCLSn 3
#define BOTn 2
#define CLSOUTn 8
#define NEXC 819              // int(1024 * 0.8)

#define NCTA 128
#define NTHR 256
#define NBC 4                 // batch groups (32 b each)
#define NJC2 32               // j slices (32 j each)

#define ALPHA_N 0.2f
#define DT_SEC 0.02f
#define NZ_SCALE 0.25f        // NOISE_STD / ALPHA_N
#define AX_SLOW ((float)(20.0 / 1500.0))
#define AX_FAST ((float)(20.0 / 200.0))

#define NR (NOUTn + NCLSn * CLSOUTn)   // 27 fused readout rows
#define PR_ROWS 32
#define CPITCH 33

// smem word offsets:
//  wh [512 kq][32 j] swizzled : 16384 words
//  wl                          : 16384 words
//  staging: 2 bufs x (hi 4096 + lo 4096) = 16384 words
//           (Cbuf 8*32*33=8448 words ALIASES the staging region after MMA)
#define SM_WH 0
#define SM_WL 16384
#define SM_ST 32768
#define SM_COMB 0             // P3 reuses everything
#define SMEM_WORDS 49152      // 192 KB
#define SMEM_BYTES (SMEM_WORDS * 4)

// ---------------- device scratch ----------------
__device__ float g_drive[(size_t)Tn * Hn * Bn];   // [t][h][b], noise folded
__device__ unsigned g_hph[2][Bn * 512];           // h_post hi pairs, B-MAJOR [b][kq]
__device__ unsigned g_hpl[2][Bn * 512];           // h_post lo pairs [b][kq]
__device__ float g_comb[NR * Hn];
__device__ float g_combb[NR];
__device__ unsigned g_count;                      // phase-transition counter
__device__ unsigned g_hbc[NBC * 32];              // h-ready per batch-group (32/step)

// ---------------- sync helpers ----------------
__device__ __forceinline__ void red_rel(unsigned* p) {
    asm volatile("red.release.gpu.global.add.u32 [%0], 1;" :: "l"(p) : "memory");
}
__device__ __forceinline__ unsigned ld_rlx(const unsigned* p) {
    unsigned v;
    asm volatile("ld.relaxed.gpu.global.u32 %0, [%1];" : "=r"(v) : "l"(p) : "memory");
    return v;
}
__device__ __forceinline__ void fence_acq() {
    asm volatile("fence.acq_rel.gpu;" ::: "memory");
}
__device__ __forceinline__ void announce(unsigned* p) {
    __syncthreads();
    if (threadIdx.x == 0) red_rel(p);
}

__device__ __forceinline__ void cp_async16(uint32_t saddr, const void* gaddr) {
    asm volatile("cp.async.cg.shared.global [%0], [%1], 16;" :: "r"(saddr), "l"(gaddr));
}
__device__ __forceinline__ void cp_commit() {
    asm volatile("cp.async.commit_group;");
}
template <int N>
__device__ __forceinline__ void cp_wait() {
    asm volatile("cp.async.wait_group %0;" :: "n"(N));
}

__device__ __forceinline__ void gbar(unsigned target) {
    __syncthreads();
    if (threadIdx.x == 0) {
        red_rel(&g_count);
        while (ld_rlx(&g_count) < target) { }
        fence_acq();
    }
    __syncthreads();
}

// bf16 split helpers
__device__ __forceinline__ unsigned pack_pair_hi(float e, float o,
                                                 float& re, float& ro) {
    __nv_bfloat16 he = __float2bfloat16(e);
    __nv_bfloat16 ho = __float2bfloat16(o);
    re = e - __bfloat162float(he);
    ro = o - __bfloat162float(ho);
    return ((unsigned)__bfloat16_as_ushort(ho) << 16) |
           (unsigned)__bfloat16_as_ushort(he);
}
__device__ __forceinline__ unsigned pack_pair(float e, float o) {
    __nv_bfloat16 he = __float2bfloat16(e);
    __nv_bfloat16 ho = __float2bfloat16(o);
    return ((unsigned)__bfloat16_as_ushort(ho) << 16) |
           (unsigned)__bfloat16_as_ushort(he);
}

#define MMA16816(cr, a0_, a1_, a2_, a3_, b0_, b1_)                          \
    asm volatile("mma.sync.aligned.m16n8k16.row.col.f32.bf16.bf16.f32 "     \
        "{%0,%1,%2,%3}, {%4,%5,%6,%7}, {%8,%9}, {%0,%1,%2,%3};"             \
        : "+f"((cr)[0]), "+f"((cr)[1]), "+f"((cr)[2]), "+f"((cr)[3])        \
        : "r"(a0_), "r"(a1_), "r"(a2_), "r"(a3_), "r"(b0_), "r"(b1_))

// ---------------- reset (graph-replay determinism) ----------------
__global__ void reset_kernel() {
    int i = threadIdx.x;
    if (i == 0) g_count = 0;
    if (i < NBC * 32) g_hbc[i] = 0;
}

// stage chunk ci (kq [128ci,+128) of 32 rows) into buffer p, xor-swizzled
#define STAGE(ci, p)                                                         \
{                                                                            \
    const uint32_t dsth = stg_addr + (p) * 32768u;                           \
    _Pragma("unroll")                                                        \
    for (int i_ = 0; i_ < 4; i_++) {                                         \
        int id_ = tid + i_ * 256;                                            \
        int r_ = id_ >> 5, ch_ = id_ & 31;                                   \
        int swc_ = ch_ ^ (r_ & 7);                                           \
        cp_async16(dsth + r_ * 512 + swc_ * 16,                              \
                   (const char*)srch + r_ * 2048 + (ci) * 512 + ch_ * 16);   \
    }                                                                        \
    _Pragma("unroll")                                                        \
    for (int i_ = 0; i_ < 4; i_++) {                                         \
        int id_ = tid + i_ * 256;                                            \
        int r_ = id_ >> 5, ch_ = id_ & 31;                                   \
        int swc_ = ch_ ^ (r_ & 7);                                           \
        cp_async16(dsth + 16384u + r_ * 512 + swc_ * 16,                     \
                   (const char*)srcl + r_ * 2048 + (ci) * 512 + ch_ * 16);   \
    }                                                                        \
    cp_commit();                                                             \
}

// MMA one chunk from buffer p; warp covers k-tiles {2w, 2w+1} of the chunk
#define MMACHUNK(ci, p)                                                      \
{                                                                            \
    const unsigned* sh_ = stg + (p) * 8192;                                  \
    const unsigned* sl_ = sh_ + 4096;                                        \
    _Pragma("unroll")                                                        \
    for (int q_ = 0; q_ < 2; q_++) {                                         \
        const int ktl_ = 2 * warp + q_;                                      \
        const int kqb_ = 8 * ktl_;                                           \
        const int colA_ = (kqb_ + la4) ^ (ld4 << 2);                         \
        unsigned ah_[2][4], al_[2][4];                                       \
        _Pragma("unroll")                                                    \
        for (int mt_ = 0; mt_ < 2; mt_++) {                                  \
            int rb_ = ld4 * 128 + mt_ * 2048;                                \
            ah_[mt_][0] = sh_[rb_ + colA_];                                  \
            ah_[mt_][1] = sh_[rb_ + 1024 + colA_];                           \
            ah_[mt_][2] = sh_[rb_ + (colA_ ^ 4)];                            \
            ah_[mt_][3] = sh_[rb_ + 1024 + (colA_ ^ 4)];                     \
            al_[mt_][0] = sl_[rb_ + colA_];                                  \
            al_[mt_][1] = sl_[rb_ + 1024 + colA_];                           \
            al_[mt_][2] = sl_[rb_ + (colA_ ^ 4)];                            \
            al_[mt_][3] = sl_[rb_ + 1024 + (colA_ ^ 4)];                     \
        }                                                                    \
        const int kqg_ = 128 * (ci) + kqb_;                                  \
        _Pragma("unroll")                                                    \
        for (int nt_ = 0; nt_ < 4; nt_++) {                                  \
            int colW_ = (8 * nt_ + ld4) ^ (la4 << 3);                        \
            unsigned bh0_ = wh[(kqg_ + la4) * 32 + colW_];                   \
            unsigned bh1_ = wh[(kqg_ + la4 + 4) * 32 + colW_];               \
            unsigned bl0_ = wl[(kqg_ + la4) * 32 + colW_];                   \
            unsigned bl1_ = wl[(kqg_ + la4 + 4) * 32 + colW_];               \
            _Pragma("unroll")                                                \
            for (int mt_ = 0; mt_ < 2; mt_++) {                              \
                MMA16816(C[mt_][nt_], ah_[mt_][0], ah_[mt_][1],              \
                         ah_[mt_][2], ah_[mt_][3], bh0_, bh1_);              \
                MMA16816(C[mt_][nt_], ah_[mt_][0], ah_[mt_][1],              \
                         ah_[mt_][2], ah_[mt_][3], bl0_, bl1_);              \
                MMA16816(C[mt_][nt_], al_[mt_][0], al_[mt_][1],              \
                         al_[mt_][2], al_[mt_][3], bh0_, bh1_);              \
            }                                                                \
        }                                                                    \
    }                                                                        \
}

// ---------------- the single persistent kernel ----------------
__global__ void __launch_bounds__(NTHR, 1) mega_kernel(
        const float* __restrict__ stim,
        const float* __restrict__ ctx,
        const float* __restrict__ w_rec,
        const float* __restrict__ b_rec,
        const float* __restrict__ w_in,
        const float* __restrict__ w_ctx,
        const float* __restrict__ w_out,
        const float* __restrict__ b_out,
        const float* __restrict__ c1_w,
        const float* __restrict__ c1_b,
        const float* __restrict__ c2_w,
        const float* __restrict__ c2_b,
        const float* __restrict__ noise,
        float* __restrict__ out0,
        float* __restrict__ acts,
        float* __restrict__ pout) {
    extern __shared__ float sm[];
    unsigned* wh = (unsigned*)(sm + SM_WH);      // [512 kq][32 j] swizzled
    unsigned* wl = (unsigned*)(sm + SM_WL);
    const unsigned* stg = (const unsigned*)(sm + SM_ST);

    const int c    = blockIdx.x;
    const int tid  = threadIdx.x;
    const int lane = tid & 31;
    const int warp = tid >> 5;
    const int la4 = lane & 3, ld4 = lane >> 2;
    // tile roles
    const int bc = c >> 5;               // batch group 0..3 (32 b rows)
    const int jc = c & 31;               // j slice 0..31 (32 j cols)
    const int bc32 = bc * 32;
    // per-thread output mapping: b-local = tid>>3, j quad = tid&7
    const int bl  = tid >> 3;            // 0..31
    const int jql = tid & 7;             // 0..7
    const int bglob = 32 * bc + bl;
    const int jgl = 32 * jc + jql * 4;   // global j base (multiple of 4)

    // ---- P0a: classifier fusion ----
    {
        int idx = c * NTHR + tid;
        if (idx < NOUTn * Hn) g_comb[idx] = w_out[idx];
        if (idx < NCLSn * CLSOUTn * Hn) {
            int r = idx / Hn, h = idx % Hn;
            int j = r / CLSOUTn, o = r % CLSOUTn;
            float acc = 0.f;
            #pragma unroll
            for (int k = 0; k < BOTn; k++)
                acc += c2_w[(j * CLSOUTn + o) * BOTn + k] * c1_w[(j * BOTn + k) * Hn + h];
            g_comb[(NOUTn + r) * Hn + h] = acc;
        }
        if (idx < NOUTn) g_combb[idx] = b_out[idx];
        if (idx >= NOUTn && idx < NR) {
            int r = idx - NOUTn;
            int j = r / CLSOUTn, o = r % CLSOUTn;
            float acc = c2_b[j * CLSOUTn + o];
            #pragma unroll
            for (int k = 0; k < BOTn; k++)
                acc += c2_w[(j * CLSOUTn + o) * BOTn + k] * c1_b[j * BOTn + k];
            g_combb[idx] = acc;
        }
    }

    // ---- P0b: W columns [32jc, +32), all k, as hi/lo bf16 k-pairs (swizzled) ----
    for (int idx = tid; idx < 512 * 32; idx += NTHR) {
        int kq = idx >> 5, jl = idx & 31;
        int j = 32 * jc + jl;
        int k0 = 2 * kq;
        float w0 = fmaxf(w_rec[(size_t)k0 * Hn + j], 0.f);
        float w1 = fmaxf(w_rec[(size_t)(k0 + 1) * Hn + j], 0.f);
        if (k0 == j) w0 = 0.f;
        if (k0 + 1 == j) w1 = 0.f;
        w0 = (k0 < NEXC) ? w0 : -w0;
        w1 = (k0 + 1 < NEXC) ? w1 : -w1;
        float r0, r1;
        int sidx = kq * 32 + (jl ^ ((kq & 3) << 3));
        wh[sidx] = pack_pair_hi(w0, w1, r0, r1);
        wl[sidx] = pack_pair(r0, r1);
    }
    float br[4];
    #pragma unroll
    for (int jj = 0; jj < 4; jj++) br[jj] = b_rec[jgl + jj];

    // ---- P0c: h_post(0) = 0 (b-major pairs), announce ----
    {
        int kq0 = jgl >> 1;              // 16jc + jql*2
        g_hph[0][(size_t)bglob * 512 + kq0]     = 0u;
        g_hph[0][(size_t)bglob * 512 + kq0 + 1] = 0u;
        g_hpl[0][(size_t)bglob * 512 + kq0]     = 0u;
        g_hpl[0][(size_t)bglob * 512 + kq0 + 1] = 0u;
    }
    announce(&g_hbc[bc32]);

    // ---- P1: drive precompute (unchanged, [t][h][b]) ----
    {
        const int gg = tid >> 7;
        const int bbb = tid & 127;
        for (int u = c; u < Tn * 4; u += NCTA) {
            const int t = u % Tn;
            const int h0 = (u / Tn) * 256 + gg * 128;

            float sin_r[Sn], cin_r[Cn];
            const float4* sp = (const float4*)(stim + ((size_t)bbb * Tn + t) * Sn);
            #pragma unroll
            for (int p = 0; p < Sn / 4; p++) {
                float4 v = sp[p];
                sin_r[4*p] = v.x; sin_r[4*p+1] = v.y; sin_r[4*p+2] = v.z; sin_r[4*p+3] = v.w;
            }
            const float4* cpp = (const float4*)(ctx + ((size_t)bbb * Tn + t) * Cn);
            #pragma unroll
            for (int p = 0; p < Cn / 4; p++) {
                float4 v = cpp[p];
                cin_r[4*p] = v.x; cin_r[4*p+1] = v.y; cin_r[4*p+2] = v.z; cin_r[4*p+3] = v.w;
            }
            const float4* nzp = (const float4*)(noise + ((size_t)t * Bn + bbb) * Hn);

            for (int hh = 0; hh < 128; hh += 4) {
                const int h = h0 + hh;
                float acc0 = 0.f, acc1 = 0.f, acc2 = 0.f, acc3 = 0.f;
                #pragma unroll
                for (int s4 = 0; s4 < Sn / 4; s4++) {
                    float4 w0 = *(const float4*)(w_in + (size_t)(h + 0) * Sn + s4 * 4);
                    float4 w1 = *(const float4*)(w_in + (size_t)(h + 1) * Sn + s4 * 4);
                    float4 w2 = *(const float4*)(w_in + (size_t)(h + 2) * Sn + s4 * 4);
                    float4 w3 = *(const float4*)(w_in + (size_t)(h + 3) * Sn + s4 * 4);
                    float i0 = sin_r[4*s4], i1 = sin_r[4*s4+1];
                    float i2 = sin_r[4*s4+2], i3 = sin_r[4*s4+3];
                    acc0 = fmaf(i0, w0.x, acc0); acc0 = fmaf(i1, w0.y, acc0);
                    acc0 = fmaf(i2, w0.z, acc0); acc0 = fmaf(i3, w0.w, acc0);
                    acc1 = fmaf(i0, w1.x, acc1); acc1 = fmaf(i1, w1.y, acc1);
                    acc1 = fmaf(i2, w1.z, acc1); acc1 = fmaf(i3, w1.w, acc1);
                    acc2 = fmaf(i0, w2.x, acc2); acc2 = fmaf(i1, w2.y, acc2);
                    acc2 = fmaf(i2, w2.z, acc2); acc2 = fmaf(i3, w2.w, acc2);
                    acc3 = fmaf(i0, w3.x, acc3); acc3 = fmaf(i1, w3.y, acc3);
                    acc3 = fmaf(i2, w3.z, acc3); acc3 = fmaf(i3, w3.w, acc3);
                }
                #pragma unroll
                for (int c4 = 0; c4 < Cn / 4; c4++) {
                    float4 w0 = *(const float4*)(w_ctx + (size_t)(h + 0) * Cn + c4 * 4);
                    float4 w1 = *(const float4*)(w_ctx + (size_t)(h + 1) * Cn + c4 * 4);
                    float4 w2 = *(const float4*)(w_ctx + (size_t)(h + 2) * Cn + c4 * 4);
                    float4 w3 = *(const float4*)(w_ctx + (size_t)(h + 3) * Cn + c4 * 4);
                    float i0 = cin_r[4*c4], i1 = cin_r[4*c4+1];
                    float i2 = cin_r[4*c4+2], i3 = cin_r[4*c4+3];
                    acc0 = fmaf(i0, w0.x, acc0); acc0 = fmaf(i1, w0.y, acc0);
                    acc0 = fmaf(i2, w0.z, acc0); acc0 = fmaf(i3, w0.w, acc0);
                    acc1 = fmaf(i0, w1.x, acc1); acc1 = fmaf(i1, w1.y, acc1);
                    acc1 = fmaf(i2, w1.z, acc1); acc1 = fmaf(i3, w1.w, acc1);
                    acc2 = fmaf(i0, w2.x, acc2); acc2 = fmaf(i1, w2.y, acc2);
                    acc2 = fmaf(i2, w2.z, acc2); acc2 = fmaf(i3, w2.w, acc2);
                    acc3 = fmaf(i0, w3.x, acc3); acc3 = fmaf(i1, w3.y, acc3);
                    acc3 = fmaf(i2, w3.z, acc3); acc3 = fmaf(i3, w3.w, acc3);
                }
                float4 nz = nzp[h >> 2];
                float* gd = g_drive + ((size_t)t * Hn + h) * Bn + bbb;
                gd[0]      = fmaf(NZ_SCALE, nz.x, acc0);
                gd[Bn]     = fmaf(NZ_SCALE, nz.y, acc1);
                gd[2 * Bn] = fmaf(NZ_SCALE, nz.z, acc2);
                gd[3 * Bn] = fmaf(NZ_SCALE, nz.w, acc3);
            }
        }
    }

    gbar(NCTA);   // drive complete

    // ---- P2: scan (one sync hop per step, closed 32-CTA batch groups) ----
    float h[4], sx[4], su[4];
    #pragma unroll
    for (int jj = 0; jj < 4; jj++) {
        h[jj] = 0.f;
        sx[jj] = 1.f;
        su[jj] = (jj & 1) ? 0.15f : 0.45f;   // jgl multiple of 4
    }

    const uint32_t stg_addr = (uint32_t)__cvta_generic_to_shared(sm + SM_ST);

    for (int step = 0; step < Tn; step++) {
        const unsigned htarget = 32u * (unsigned)(step + 1);
        const int par = step & 1;

        // drive prefetch (overlaps the flag wait)
        const float* gd = g_drive + ((size_t)step * Hn + jgl) * Bn + bglob;
        float d0 = __ldcg(gd), d1 = __ldcg(gd + Bn);
        float d2 = __ldcg(gd + 2 * Bn), d3 = __ldcg(gd + 3 * Bn);

        // ---- wait: my batch group's h rows ready (covers RAW and WAR) ----
        if (tid == 0) {
            while (ld_rlx(&g_hbc[bc32]) < htarget) { }
            fence_acq();
        }
        __syncthreads();

        const unsigned* srch = g_hph[par] + (size_t)(32 * bc) * 512;
        const unsigned* srcl = g_hpl[par] + (size_t)(32 * bc) * 512;

        float C[2][4][4];
        #pragma unroll
        for (int mt = 0; mt < 2; mt++)
            #pragma unroll
            for (int nt = 0; nt < 4; nt++) {
                C[mt][nt][0] = 0.f; C[mt][nt][1] = 0.f;
                C[mt][nt][2] = 0.f; C[mt][nt][3] = 0.f;
            }

        STAGE(0, 0)
        STAGE(1, 1)

        cp_wait<1>(); __syncthreads();
        MMACHUNK(0, 0)
        __syncthreads();
        STAGE(2, 0)

        cp_wait<1>(); __syncthreads();
        MMACHUNK(1, 1)
        __syncthreads();
        STAGE(3, 1)

        cp_wait<1>(); __syncthreads();
        MMACHUNK(2, 0)

        cp_wait<0>(); __syncthreads();
        MMACHUNK(3, 1)
        __syncthreads();          // all MMA reads done before Cbuf aliases staging

        // ---- cross-warp reduce via Cbuf (aliases staging region) ----
        {
            float* cb = sm + SM_ST + warp * (32 * CPITCH);
            #pragma unroll
            for (int mt = 0; mt < 2; mt++)
                #pragma unroll
                for (int nt = 0; nt < 4; nt++) {
                    int r0 = (16 * mt + ld4) * CPITCH + 8 * nt + 2 * la4;
                    cb[r0]     = C[mt][nt][0];
                    cb[r0 + 1] = C[mt][nt][1];
                    cb[r0 + 8 * CPITCH]     = C[mt][nt][2];
                    cb[r0 + 8 * CPITCH + 1] = C[mt][nt][3];
                }
        }
        __syncthreads();

        float s0 = 0.f, s1 = 0.f, s2 = 0.f, s3 = 0.f;
        {
            const float* cbb = sm + SM_ST;
            #pragma unroll
            for (int w2 = 0; w2 < 8; w2++) {
                const float* p = cbb + w2 * (32 * CPITCH) + bl * CPITCH + jql * 4;
                s0 += p[0]; s1 += p[1]; s2 += p[2]; s3 += p[3];
            }
        }

        float ss[4] = {s0, s1, s2, s3};
        float dd[4] = {d0, d1, d2, d3};
        float hn[4], hp[4];
        #pragma unroll
        for (int jj = 0; jj < 4; jj++) {
            float val = h[jj] * (1.f - ALPHA_N)
                      + ALPHA_N * (dd[jj] + ss[jj] + br[jj]);
            hn[jj] = fmaxf(val, 0.f);
            h[jj] = hn[jj];
        }
        // STP + h_post(step+1) pairs (b-major), announce, then acts store
        #pragma unroll
        for (int jj = 0; jj < 4; jj++) {
            const float axv = (jj & 1) ? AX_FAST : AX_SLOW;
            const float Uv  = (jj & 1) ? 0.15f : 0.45f;
            float hh = h[jj];
            float sxo = sx[jj], suo = su[jj];
            float sxn = sxo + axv * (1.f - sxo) - DT_SEC * suo * sxo * hh;
            float sun = suo + axv * (Uv - suo) + DT_SEC * Uv * (1.f - suo) * hh;
            sxn = fminf(fmaxf(sxn, 0.f), 1.f);
            sun = fminf(fmaxf(sun, 0.f), 1.f);
            sx[jj] = sxn; su[jj] = sun;
            hp[jj] = sun * sxn * hh;
        }
        {
            unsigned* dh = g_hph[par ^ 1];
            unsigned* dl = g_hpl[par ^ 1];
            int kq0 = jgl >> 1;
            float r0, r1, r2, r3;
            unsigned h01 = pack_pair_hi(hp[0], hp[1], r0, r1);
            unsigned h23 = pack_pair_hi(hp[2], hp[3], r2, r3);
            dh[(size_t)bglob * 512 + kq0]     = h01;
            dh[(size_t)bglob * 512 + kq0 + 1] = h23;
            dl[(size_t)bglob * 512 + kq0]     = pack_pair(r0, r1);
            dl[(size_t)bglob * 512 + kq0 + 1] = pack_pair(r2, r3);
        }
        announce(&g_hbc[bc32]);

        *(float4*)(acts + ((size_t)bglob * Tn + step) * Hn + jgl) =
            make_float4(hn[0], hn[1], hn[2], hn[3]);
    }

    gbar(2 * NCTA);   // scan complete

    // ---- P3: post (fused readout) ----
    {
        float* s_comb = sm + SM_COMB;
        for (int i = tid; i < NR * Hn; i += NTHR) s_comb[i] = g_comb[i];
        __syncthreads();

        const float4* comb4 = (const float4*)s_comb;

        for (int u = c; u < (Bn * Tn) / PR_ROWS; u += NCTA) {
            #pragma unroll 1
            for (int rr = 0; rr < 4; rr++) {
                const int bt = u * PR_ROWS + warp * 4 + rr;
                const float4* a4 = (const float4*)(acts + (size_t)bt * Hn);

                float acc[NR];
                #pragma unroll
                for (int r = 0; r < NR; r++) acc[r] = 0.f;

                #pragma unroll
                for (int it = 0; it < Hn / 128; it++) {
                    float4 a = a4[it * 32 + lane];
                    #pragma unroll
                    for (int r = 0; r < NR; r++) {
                        float4 ww = comb4[r * 256 + it * 32 + lane];
                        float s = a.x * ww.x + a.y * ww.y;
                        s = fmaf(a.z, ww.z, s);
                        s = fmaf(a.w, ww.w, s);
                        acc[r] += s;
                    }
                }
                #pragma unroll
                for (int r = 0; r < NR; r++) {
                    #pragma unroll
                    for (int off = 16; off > 0; off >>= 1)
                        acc[r] += __shfl_down_sync(0xffffffffu, acc[r], off);
                }
                if (lane == 0) {
                    #pragma unroll
                    for (int r = 0; r < NOUTn; r++)
                        out0[(size_t)bt * NOUTn + r] = acc[r] + g_combb[r];
                    #pragma unroll
                    for (int r = NOUTn; r < NR; r++)
                        pout[(size_t)bt * (NCLSn * CLSOUTn) + (r - NOUTn)]
                            = acc[r] + g_combb[r];
                }
            }
        }
    }
}

// ---------------- launch ----------------
extern "C" void kernel_launch(void* const* d_in, const int* in_sizes, int n_in,
                              void* d_out, int out_size) {
    const float* stim  = (const float*)d_in[0];
    const float* ctx   = (const float*)d_in[1];
    const float* w_rec = (const float*)d_in[2];
    const float* b_rec = (const float*)d_in[3];
    const float* w_in  = (const float*)d_in[4];
    const float* w_ctx = (const float*)d_in[5];
    const float* w_out = (const float*)d_in[6];
    const float* b_out = (const float*)d_in[7];
    const float* c1_w  = (const float*)d_in[8];
    const float* c1_b  = (const float*)d_in[9];
    const float* c2_w  = (const float*)d_in[10];
    const float* c2_b  = (const float*)d_in[11];
    const float* noise = (const float*)d_in[12];

    float* out0 = (float*)d_out;                         // [B, T, 3]
    float* acts = out0 + (size_t)Bn * Tn * NOUTn;        // [B, T, H]
    float* pout = acts + (size_t)Bn * Tn * Hn;           // [B, T, 3, 8]

    static bool attr_set = false;
    if (!attr_set) {
        cudaFuncSetAttribute(mega_kernel,
                             cudaFuncAttributeMaxDynamicSharedMemorySize,
                             SMEM_BYTES);
        attr_set = true;
    }

    reset_kernel<<<1, 256>>>();   // covers g_count + all 128 g_hbc words
    mega_kernel<<<NCTA, NTHR, SMEM_BYTES>>>(
        stim, ctx, w_rec, b_rec, w_in, w_ctx, w_out, b_out,
        c1_w, c1_b, c2_w, c2_b, noise, out0, acts, pout);
}